// round 5
// baseline (speedup 1.0000x reference)
#include <cuda_runtime.h>
#include <cstdint>

#define NMAX 50000
#define EMAX 800000

// ---------------- scratch (device globals: no runtime allocation) -------------
__device__ int   g_cnt[2][NMAX];
__device__ int   g_offs[2][NMAX + 1];
__device__ int   g_cursor[2][NMAX];
__device__ int   g_rows[2][EMAX];
__device__ float g_dinv[2][NMAX];

__device__ float g_R0[NMAX * 64];
__device__ float g_y [NMAX * 64];
__device__ float g_R1[NMAX * 128];
__device__ float g_R2[NMAX * 128];
__device__ float g_R3[NMAX * 128];

// ---------------- CSR build ---------------------------------------------------
__global__ void zero_cnt_kernel(int n) {
    int i = blockIdx.x * blockDim.x + threadIdx.x;
    if (i < 2 * n) (&g_cnt[0][0])[i] = 0;
}

__global__ void hist_kernel(const int* __restrict__ ei1, const int* __restrict__ ei2, int E) {
    int e = blockIdx.x * blockDim.x + threadIdx.x;
    if (e < E) {
        atomicAdd(&g_cnt[0][ei1[E + e]], 1);
        atomicAdd(&g_cnt[1][ei2[E + e]], 1);
    }
}

__global__ void dinv_kernel(int n) {
    int i = blockIdx.x * blockDim.x + threadIdx.x;
    if (i < n) {
        int c0 = g_cnt[0][i], c1 = g_cnt[1][i];
        g_dinv[0][i] = c0 > 0 ? rsqrtf((float)c0) : 0.f;
        g_dinv[1][i] = c1 > 0 ? rsqrtf((float)c1) : 0.f;
    }
}

// one block per graph; exclusive scan of cnt -> offs & cursor
__global__ void scan_kernel(int n) {
    const int g = blockIdx.x;
    const int* cnt = g_cnt[g];
    int* offs = g_offs[g];
    int* cur  = g_cursor[g];
    __shared__ int warpsums[32];
    __shared__ int s_carry;
    const int lane = threadIdx.x & 31;
    const int wid  = threadIdx.x >> 5;
    if (threadIdx.x == 0) s_carry = 0;
    __syncthreads();
    for (int base = 0; base < n; base += blockDim.x) {
        int i = base + threadIdx.x;
        int v = (i < n) ? cnt[i] : 0;
        int s = v;
        #pragma unroll
        for (int o = 1; o < 32; o <<= 1) {
            int t = __shfl_up_sync(0xffffffffu, s, o);
            if (lane >= o) s += t;
        }
        if (lane == 31) warpsums[wid] = s;
        __syncthreads();
        if (wid == 0) {
            int ws = warpsums[lane];
            #pragma unroll
            for (int o = 1; o < 32; o <<= 1) {
                int t = __shfl_up_sync(0xffffffffu, ws, o);
                if (lane >= o) ws += t;
            }
            warpsums[lane] = ws;   // inclusive warp-prefix
        }
        __syncthreads();
        int warpoff = (wid > 0) ? warpsums[wid - 1] : 0;
        int excl = s - v + warpoff + s_carry;
        if (i < n) { offs[i] = excl; cur[i] = excl; }
        __syncthreads();                        // all read s_carry before update
        if (threadIdx.x == blockDim.x - 1) s_carry += warpsums[31];
        __syncthreads();
    }
    if (threadIdx.x == 0) offs[n] = s_carry;
}

__global__ void scatter_kernel(const int* __restrict__ ei1, const int* __restrict__ ei2, int E) {
    int e = blockIdx.x * blockDim.x + threadIdx.x;
    if (e < E) {
        int c = ei1[E + e];
        int p = atomicAdd(&g_cursor[0][c], 1);
        g_rows[0][p] = ei1[e];
        c = ei2[E + e];
        p = atomicAdd(&g_cursor[1][c], 1);
        g_rows[1][p] = ei2[e];
    }
}

// ---------------- GEMM: Y[M,64] = X[M,KDIM] @ W[KDIM,64] (+bias, relu) --------
template<int KDIM, bool RELU_BIAS>
__global__ __launch_bounds__(256) void gemm_kernel(
    const float* __restrict__ X, const float* __restrict__ W,
    const float* __restrict__ bias, float* __restrict__ Y, int M)
{
    __shared__ float Xs[128][64];
    __shared__ float Ws[64][64];
    const int row0 = blockIdx.x * 128;
    const int tx = threadIdx.x & 7;    // col group of 8
    const int ty = threadIdx.x >> 3;   // row group of 4

    float acc[4][8];
    #pragma unroll
    for (int i = 0; i < 4; i++)
        #pragma unroll
        for (int j = 0; j < 8; j++) acc[i][j] = 0.f;

    #pragma unroll
    for (int kt = 0; kt < KDIM; kt += 64) {
        // X tile (128 x 64), coalesced float4
        #pragma unroll
        for (int t = 0; t < 8; t++) {
            int idx = threadIdx.x + t * 256;        // 0..2047
            int r = idx >> 4;
            int kq = (idx & 15) << 2;
            float4 v = make_float4(0.f, 0.f, 0.f, 0.f);
            int gr = row0 + r;
            if (gr < M) v = *(const float4*)(X + (size_t)gr * KDIM + kt + kq);
            *(float4*)&Xs[r][kq] = v;
        }
        // W tile (64 x 64)
        #pragma unroll
        for (int t = 0; t < 4; t++) {
            int idx = threadIdx.x + t * 256;        // 0..1023
            int r = idx >> 4;
            int kq = (idx & 15) << 2;
            *(float4*)&Ws[r][kq] = *(const float4*)(W + (size_t)(kt + r) * 64 + kq);
        }
        __syncthreads();
        #pragma unroll 8
        for (int k = 0; k < 64; k++) {
            float4 b0 = *(const float4*)&Ws[k][tx * 8];
            float4 b1 = *(const float4*)&Ws[k][tx * 8 + 4];
            #pragma unroll
            for (int i = 0; i < 4; i++) {
                float a = Xs[ty * 4 + i][k];
                acc[i][0] += a * b0.x; acc[i][1] += a * b0.y;
                acc[i][2] += a * b0.z; acc[i][3] += a * b0.w;
                acc[i][4] += a * b1.x; acc[i][5] += a * b1.y;
                acc[i][6] += a * b1.z; acc[i][7] += a * b1.w;
            }
        }
        __syncthreads();
    }

    float4 bb0 = make_float4(0.f, 0.f, 0.f, 0.f), bb1 = bb0;
    if (RELU_BIAS) {
        bb0 = *(const float4*)(bias + tx * 8);
        bb1 = *(const float4*)(bias + tx * 8 + 4);
    }
    #pragma unroll
    for (int i = 0; i < 4; i++) {
        int gr = row0 + ty * 4 + i;
        if (gr < M) {
            float4 o0 = make_float4(acc[i][0], acc[i][1], acc[i][2], acc[i][3]);
            float4 o1 = make_float4(acc[i][4], acc[i][5], acc[i][6], acc[i][7]);
            if (RELU_BIAS) {
                o0.x = fmaxf(o0.x + bb0.x, 0.f); o0.y = fmaxf(o0.y + bb0.y, 0.f);
                o0.z = fmaxf(o0.z + bb0.z, 0.f); o0.w = fmaxf(o0.w + bb0.w, 0.f);
                o1.x = fmaxf(o1.x + bb1.x, 0.f); o1.y = fmaxf(o1.y + bb1.y, 0.f);
                o1.z = fmaxf(o1.z + bb1.z, 0.f); o1.w = fmaxf(o1.w + bb1.w, 0.f);
            }
            *(float4*)(Y + (size_t)gr * 64 + tx * 8) = o0;
            *(float4*)(Y + (size_t)gr * 64 + tx * 8 + 4) = o1;
        }
    }
}

// ---------------- aggregation: out[n][f] = b[f] + sum_e dinv[n]*dinv[row]*y[row][f]
// one warp per destination node, 2 features per lane (float2), CSR gather, no atomics
__global__ __launch_bounds__(256) void agg_kernel(
    const float* __restrict__ y, int g, const float* __restrict__ bias,
    float* __restrict__ out /* pre-offset to half; stride 128 */, int n)
{
    int node = (blockIdx.x * blockDim.x + threadIdx.x) >> 5;
    if (node >= n) return;
    const int lane = threadIdx.x & 31;
    const int* __restrict__ offs = g_offs[g];
    const int* __restrict__ rows = g_rows[g];
    const float* __restrict__ dinv = g_dinv[g];

    int s = offs[node], e = offs[node + 1];
    float dc = dinv[node];
    float ax = 0.f, ay = 0.f;
    for (int i = s; i < e; i++) {
        int r = rows[i];
        float nrm = dc * dinv[r];
        float2 v = *(const float2*)(y + (size_t)r * 64 + 2 * lane);
        ax += v.x * nrm;
        ay += v.y * nrm;
    }
    float2 b2 = *(const float2*)(bias + 2 * lane);
    float2 o = make_float2(ax + b2.x, ay + b2.y);
    *(float2*)(out + (size_t)node * 128 + 2 * lane) = o;
}

// ---------------- readout -----------------------------------------------------
__global__ __launch_bounds__(256) void readout_kernel(
    const float* __restrict__ Wr0, const float* __restrict__ br0,
    const float* __restrict__ Wr1, const float* __restrict__ br1,
    const float* __restrict__ Wr2, const float* __restrict__ br2,
    const float* __restrict__ Wr3, const float* __restrict__ br3,
    const float* __restrict__ w0, const float* __restrict__ w1,
    const float* __restrict__ w2, const float* __restrict__ w3,
    float* __restrict__ out, int n)
{
    int node = (blockIdx.x * blockDim.x + threadIdx.x) >> 5;
    if (node >= n) return;
    const int lane = threadIdx.x & 31;
    float W0 = w0[0], W1 = w1[0], W2 = w2[0], W3 = w3[0];
    float p = 0.f;
    {
        float2 r = *(const float2*)(g_R0 + (size_t)node * 64 + 2 * lane);
        float2 w = *(const float2*)(Wr0 + 2 * lane);
        p += W0 * (r.x * w.x + r.y * w.y);
    }
    {
        float4 r = *(const float4*)(g_R1 + (size_t)node * 128 + 4 * lane);
        float4 w = *(const float4*)(Wr1 + 4 * lane);
        p += W1 * (r.x * w.x + r.y * w.y + r.z * w.z + r.w * w.w);
    }
    {
        float4 r = *(const float4*)(g_R2 + (size_t)node * 128 + 4 * lane);
        float4 w = *(const float4*)(Wr2 + 4 * lane);
        p += W2 * (r.x * w.x + r.y * w.y + r.z * w.z + r.w * w.w);
    }
    {
        float4 r = *(const float4*)(g_R3 + (size_t)node * 128 + 4 * lane);
        float4 w = *(const float4*)(Wr3 + 4 * lane);
        p += W3 * (r.x * w.x + r.y * w.y + r.z * w.z + r.w * w.w);
    }
    #pragma unroll
    for (int o = 16; o; o >>= 1) p += __shfl_xor_sync(0xffffffffu, p, o);
    if (lane == 0)
        out[node] = p + W0 * br0[0] + W1 * br1[0] + W2 * br2[0] + W3 * br3[0];
}

// ---------------- launch ------------------------------------------------------
extern "C" void kernel_launch(void* const* d_in, const int* in_sizes, int n_in,
                              void* d_out, int out_size)
{
    const float* x    = (const float*)d_in[0];
    const int*   ei1  = (const int*)d_in[1];
    const int*   ei2  = (const int*)d_in[2];
    const float* W_in = (const float*)d_in[3];
    const float* b_in = (const float*)d_in[4];
    const float* W11  = (const float*)d_in[5];
    const float* b11  = (const float*)d_in[6];
    const float* W12  = (const float*)d_in[7];
    const float* b12  = (const float*)d_in[8];
    const float* W21  = (const float*)d_in[9];
    const float* b21  = (const float*)d_in[10];
    const float* W22  = (const float*)d_in[11];
    const float* b22  = (const float*)d_in[12];
    const float* W31  = (const float*)d_in[13];
    const float* b31  = (const float*)d_in[14];
    const float* W32  = (const float*)d_in[15];
    const float* b32  = (const float*)d_in[16];
    const float* Wr0  = (const float*)d_in[17];
    const float* br0  = (const float*)d_in[18];
    const float* Wr1  = (const float*)d_in[19];
    const float* br1  = (const float*)d_in[20];
    const float* Wr2  = (const float*)d_in[21];
    const float* br2  = (const float*)d_in[22];
    const float* Wr3  = (const float*)d_in[23];
    const float* br3  = (const float*)d_in[24];
    const float* w0   = (const float*)d_in[25];
    const float* w1   = (const float*)d_in[26];
    const float* w2   = (const float*)d_in[27];
    const float* w3   = (const float*)d_in[28];
    float* out = (float*)d_out;

    const int n = in_sizes[0] / 64;
    const int E = in_sizes[1] / 2;

    const int TB = 256;
    const int gE = (E + TB - 1) / TB;
    const int gN = (n + TB - 1) / TB;
    const int gW = (n * 32 + TB - 1) / TB;     // warp-per-node grids
    const int gG = (n + 127) / 128;            // gemm grids

    // device pointers to scratch (symbol references resolved in device code)
    float* R0 = nullptr; float* Y = nullptr; float* R1 = nullptr;
    float* R2 = nullptr; float* R3 = nullptr;
    // use cudaGetSymbolAddress once per call (pure lookup, capture-safe)
    cudaGetSymbolAddress((void**)&R0, g_R0);
    cudaGetSymbolAddress((void**)&Y,  g_y);
    cudaGetSymbolAddress((void**)&R1, g_R1);
    cudaGetSymbolAddress((void**)&R2, g_R2);
    cudaGetSymbolAddress((void**)&R3, g_R3);

    // --- CSR build for both graphs ---
    zero_cnt_kernel<<<(2 * n + TB - 1) / TB, TB>>>(n);
    hist_kernel<<<gE, TB>>>(ei1, ei2, E);
    dinv_kernel<<<gN, TB>>>(n);
    scan_kernel<<<2, 1024>>>(n);
    scatter_kernel<<<gE, TB>>>(ei1, ei2, E);

    // --- R0 = relu(x @ W_in + b_in) ---
    gemm_kernel<64, true><<<gG, TB>>>(x, W_in, b_in, R0, n);

    // --- layer 1 ---
    gemm_kernel<64, false><<<gG, TB>>>(R0, W11, nullptr, Y, n);
    agg_kernel<<<gW, TB>>>(Y, 0, b11, R1, n);
    gemm_kernel<64, false><<<gG, TB>>>(R0, W12, nullptr, Y, n);
    agg_kernel<<<gW, TB>>>(Y, 1, b12, R1 + 64, n);

    // --- layer 2 ---
    gemm_kernel<128, false><<<gG, TB>>>(R1, W21, nullptr, Y, n);
    agg_kernel<<<gW, TB>>>(Y, 0, b21, R2, n);
    gemm_kernel<128, false><<<gG, TB>>>(R1, W22, nullptr, Y, n);
    agg_kernel<<<gW, TB>>>(Y, 1, b22, R2 + 64, n);

    // --- layer 3 ---
    gemm_kernel<128, false><<<gG, TB>>>(R2, W31, nullptr, Y, n);
    agg_kernel<<<gW, TB>>>(Y, 0, b31, R3, n);
    gemm_kernel<128, false><<<gG, TB>>>(R2, W32, nullptr, Y, n);
    agg_kernel<<<gW, TB>>>(Y, 1, b32, R3 + 64, n);

    // --- readout ---
    readout_kernel<<<gW, TB>>>(Wr0, br0, Wr1, br1, Wr2, br2, Wr3, br3,
                               w0, w1, w2, w3, out, n);
}

// round 7
// speedup vs baseline: 1.3752x; 1.3752x over previous
#include <cuda_runtime.h>
#include <cstdint>

#define NMAX 50000
#define EMAX 800000

// ---------------- scratch (device globals: no runtime allocation) -------------
__device__ int   g_cnt[2][NMAX];
__device__ int   g_offs[2][NMAX + 1];
__device__ int   g_cursor[2][NMAX];
__device__ int   g_rows[2][EMAX];
__device__ float g_dinv[2][NMAX];
__device__ int   g_bsum[2][64];

__device__ float g_R0[NMAX * 64];
__device__ float g_y [NMAX * 128];
__device__ float g_R1[NMAX * 128];
__device__ float g_R2[NMAX * 128];
__device__ float g_R3[NMAX * 128];

// ---------------- CSR build ---------------------------------------------------
__global__ void zero_cnt_kernel(int n) {
    int i = blockIdx.x * blockDim.x + threadIdx.x;
    if (i < 2 * n) (&g_cnt[0][0])[i] = 0;
}

__global__ void hist_kernel(const int* __restrict__ ei1, const int* __restrict__ ei2, int E) {
    int e = blockIdx.x * blockDim.x + threadIdx.x;
    if (e < E) {
        atomicAdd(&g_cnt[0][ei1[E + e]], 1);
        atomicAdd(&g_cnt[1][ei2[E + e]], 1);
    }
}

// phase 1: per-chunk (4096-elem) sums. grid = 2*nch blocks of 256.
__global__ void scan_partial(int n, int nch) {
    int b = blockIdx.x;
    int g = b / nch, c = b % nch;
    const int* __restrict__ cnt = g_cnt[g];
    int i0 = c * 4096 + threadIdx.x * 16;
    int tot = 0;
    #pragma unroll
    for (int j = 0; j < 16; j++) {
        int i = i0 + j;
        if (i < n) tot += cnt[i];
    }
    #pragma unroll
    for (int o = 16; o; o >>= 1) tot += __shfl_xor_sync(0xffffffffu, tot, o);
    __shared__ int ws[8];
    if ((threadIdx.x & 31) == 0) ws[threadIdx.x >> 5] = tot;
    __syncthreads();
    if (threadIdx.x == 0) {
        int s = 0;
        #pragma unroll
        for (int k = 0; k < 8; k++) s += ws[k];
        g_bsum[g][c] = s;
    }
}

// phase 2: exclusive scan of the <=32 chunk sums per graph; write offs[n]=total
__global__ void scan_bsum(int n, int nch) {
    int g = threadIdx.x >> 5;
    int lane = threadIdx.x & 31;
    if (g >= 2) return;
    int v = (lane < nch) ? g_bsum[g][lane] : 0;
    int s = v;
    #pragma unroll
    for (int o = 1; o < 32; o <<= 1) {
        int t = __shfl_up_sync(0xffffffffu, s, o);
        if (lane >= o) s += t;
    }
    if (lane < nch) g_bsum[g][lane] = s - v;  // exclusive
    if (lane == 31) g_offs[g][n] = s;         // total
}

// phase 3: per-chunk rescan -> offs, cursor; also dinv. grid = 2*nch blocks.
__global__ void scan_final(int n, int nch) {
    int b = blockIdx.x;
    int g = b / nch, c = b % nch;
    const int* __restrict__ cnt = g_cnt[g];
    int* __restrict__ offs = g_offs[g];
    int* __restrict__ cur  = g_cursor[g];
    float* __restrict__ dinv = g_dinv[g];
    int base = g_bsum[g][c];
    int i0 = c * 4096 + threadIdx.x * 16;

    int v[16];
    int tsum = 0;
    #pragma unroll
    for (int j = 0; j < 16; j++) {
        int i = i0 + j;
        v[j] = (i < n) ? cnt[i] : 0;
        tsum += v[j];
    }
    // block exclusive scan of tsum over 256 threads
    const int lane = threadIdx.x & 31;
    const int wid  = threadIdx.x >> 5;
    int s = tsum;
    #pragma unroll
    for (int o = 1; o < 32; o <<= 1) {
        int t = __shfl_up_sync(0xffffffffu, s, o);
        if (lane >= o) s += t;
    }
    __shared__ int ws[8];
    if (lane == 31) ws[wid] = s;
    __syncthreads();
    int woff = 0;
    if (wid > 0) {
        #pragma unroll
        for (int k = 0; k < 7; k++) if (k < wid) woff += ws[k];
    }
    int run = base + woff + (s - tsum);
    #pragma unroll
    for (int j = 0; j < 16; j++) {
        int i = i0 + j;
        if (i < n) {
            offs[i] = run;
            cur[i]  = run;
            dinv[i] = v[j] > 0 ? rsqrtf((float)v[j]) : 0.f;
        }
        run += v[j];
    }
}

__global__ void scatter_kernel(const int* __restrict__ ei1, const int* __restrict__ ei2, int E) {
    int e = blockIdx.x * blockDim.x + threadIdx.x;
    if (e < E) {
        int c = ei1[E + e];
        int p = atomicAdd(&g_cursor[0][c], 1);
        g_rows[0][p] = ei1[e];
        c = ei2[E + e];
        p = atomicAdd(&g_cursor[1][c], 1);
        g_rows[1][p] = ei2[e];
    }
}

// ---------------- GEMM --------------------------------------------------------
// Tile 128 rows. DUAL: two weight matrices [KDIM,64] -> Y[M,128] (Ya|Yb), no bias.
// !DUAL: single [KDIM,64] -> Y[M,64] with bias+relu (for R0).
// 256 threads; each thread: 8 rows (ty*4 & 64+ty*4) x 8 cols (txc in A-half & B-half).
template<int KDIM, bool DUAL>
__global__ __launch_bounds__(256, 2) void gemm2_kernel(
    const float* __restrict__ X, const float* __restrict__ Wa,
    const float* __restrict__ Wb, const float* __restrict__ bias,
    float* __restrict__ Y, int M)
{
    constexpr int NB = DUAL ? 128 : 64;
    __shared__ float Xs[128][36];   // k-tile 32, pad to 36 floats
    __shared__ float Ws[32][NB];

    const int row0 = blockIdx.x * 128;
    const int tx = threadIdx.x & 15;
    const int ty = threadIdx.x >> 4;
    const int txc = tx * 4;
    const int tyr = ty * 4;

    float accTA[4][4] = {}, accBA[4][4] = {};
    float accTB[4][4] = {}, accBB[4][4] = {};

    for (int kt = 0; kt < KDIM; kt += 32) {
        // X tile: 128 x 32, coalesced float4 reads, stores amortized over 32 k's
        #pragma unroll
        for (int p = 0; p < 4; p++) {
            int f = threadIdx.x + p * 256;       // 0..1023
            int r = f >> 3, kq = (f & 7) * 4;
            float4 v = make_float4(0.f, 0.f, 0.f, 0.f);
            if (row0 + r < M)
                v = *(const float4*)(X + (size_t)(row0 + r) * KDIM + kt + kq);
            *(float4*)&Xs[r][kq] = v;
        }
        // W tile(s)
        if (DUAL) {
            #pragma unroll
            for (int p = 0; p < 4; p++) {
                int f = threadIdx.x + p * 256;   // 0..1023
                int k = f >> 5, cq = (f & 31) * 4;
                float4 v = (cq < 64)
                    ? *(const float4*)(Wa + (size_t)(kt + k) * 64 + cq)
                    : *(const float4*)(Wb + (size_t)(kt + k) * 64 + (cq - 64));
                *(float4*)&Ws[k][cq] = v;
            }
        } else {
            #pragma unroll
            for (int p = 0; p < 2; p++) {
                int f = threadIdx.x + p * 256;   // 0..511
                int k = f >> 4, cq = (f & 15) * 4;
                *(float4*)&Ws[k][cq] = *(const float4*)(Wa + (size_t)(kt + k) * 64 + cq);
            }
        }
        __syncthreads();

        #pragma unroll 4
        for (int k = 0; k < 32; k++) {
            float4 bA = *(const float4*)&Ws[k][txc];
            float4 bB;
            if (DUAL) bB = *(const float4*)&Ws[k][64 + txc];
            #pragma unroll
            for (int r = 0; r < 4; r++) {
                float aT = Xs[tyr + r][k];
                float aB = Xs[64 + tyr + r][k];
                accTA[r][0] += aT * bA.x; accTA[r][1] += aT * bA.y;
                accTA[r][2] += aT * bA.z; accTA[r][3] += aT * bA.w;
                accBA[r][0] += aB * bA.x; accBA[r][1] += aB * bA.y;
                accBA[r][2] += aB * bA.z; accBA[r][3] += aB * bA.w;
                if (DUAL) {
                    accTB[r][0] += aT * bB.x; accTB[r][1] += aT * bB.y;
                    accTB[r][2] += aT * bB.z; accTB[r][3] += aT * bB.w;
                    accBB[r][0] += aB * bB.x; accBB[r][1] += aB * bB.y;
                    accBB[r][2] += aB * bB.z; accBB[r][3] += aB * bB.w;
                }
            }
        }
        __syncthreads();
    }

    if (DUAL) {
        #pragma unroll
        for (int r = 0; r < 4; r++) {
            int gT = row0 + tyr + r;
            if (gT < M) {
                *(float4*)(Y + (size_t)gT * 128 + txc) =
                    make_float4(accTA[r][0], accTA[r][1], accTA[r][2], accTA[r][3]);
                *(float4*)(Y + (size_t)gT * 128 + 64 + txc) =
                    make_float4(accTB[r][0], accTB[r][1], accTB[r][2], accTB[r][3]);
            }
            int gB = row0 + 64 + tyr + r;
            if (gB < M) {
                *(float4*)(Y + (size_t)gB * 128 + txc) =
                    make_float4(accBA[r][0], accBA[r][1], accBA[r][2], accBA[r][3]);
                *(float4*)(Y + (size_t)gB * 128 + 64 + txc) =
                    make_float4(accBB[r][0], accBB[r][1], accBB[r][2], accBB[r][3]);
            }
        }
    } else {
        float4 bb = *(const float4*)(bias + txc);
        #pragma unroll
        for (int r = 0; r < 4; r++) {
            int gT = row0 + tyr + r;
            if (gT < M) {
                float4 o = make_float4(fmaxf(accTA[r][0] + bb.x, 0.f),
                                       fmaxf(accTA[r][1] + bb.y, 0.f),
                                       fmaxf(accTA[r][2] + bb.z, 0.f),
                                       fmaxf(accTA[r][3] + bb.w, 0.f));
                *(float4*)(Y + (size_t)gT * 64 + txc) = o;
            }
            int gB = row0 + 64 + tyr + r;
            if (gB < M) {
                float4 o = make_float4(fmaxf(accBA[r][0] + bb.x, 0.f),
                                       fmaxf(accBA[r][1] + bb.y, 0.f),
                                       fmaxf(accBA[r][2] + bb.z, 0.f),
                                       fmaxf(accBA[r][3] + bb.w, 0.f));
                *(float4*)(Y + (size_t)gB * 64 + txc) = o;
            }
        }
    }
}

// ---------------- fused dual-graph aggregation --------------------------------
// y: [M,128] (Ya|Yb). Warp w<n: graph 0 on cols 0-63 -> R[:,0:64];
// w>=n: graph 1 on cols 64-127 -> R[:,64:128]. One warp per node, float2/lane.
__global__ __launch_bounds__(256) void agg2_kernel(
    const float* __restrict__ y,
    const float* __restrict__ biasA, const float* __restrict__ biasB,
    float* __restrict__ R, int n)
{
    int w = (blockIdx.x * blockDim.x + threadIdx.x) >> 5;
    if (w >= 2 * n) return;
    const int g = (w >= n) ? 1 : 0;
    const int node = w - g * n;
    const int lane = threadIdx.x & 31;

    const int* __restrict__ offs = g_offs[g];
    const int* __restrict__ rows = g_rows[g];
    const float* __restrict__ dinv = g_dinv[g];
    const float* __restrict__ ys = y + g * 64 + 2 * lane;

    int s = offs[node], e = offs[node + 1];
    float dc = dinv[node];
    float ax = 0.f, ay = 0.f;
    int i = s;
    for (; i + 4 <= e; i += 4) {
        int r0 = rows[i], r1 = rows[i + 1], r2 = rows[i + 2], r3 = rows[i + 3];
        float2 v0 = *(const float2*)(ys + (size_t)r0 * 128);
        float2 v1 = *(const float2*)(ys + (size_t)r1 * 128);
        float2 v2 = *(const float2*)(ys + (size_t)r2 * 128);
        float2 v3 = *(const float2*)(ys + (size_t)r3 * 128);
        float n0 = dc * dinv[r0], n1 = dc * dinv[r1];
        float n2 = dc * dinv[r2], n3 = dc * dinv[r3];
        ax += v0.x * n0 + v1.x * n1 + v2.x * n2 + v3.x * n3;
        ay += v0.y * n0 + v1.y * n1 + v2.y * n2 + v3.y * n3;
    }
    for (; i < e; i++) {
        int r = rows[i];
        float nm = dc * dinv[r];
        float2 v = *(const float2*)(ys + (size_t)r * 128);
        ax += v.x * nm;
        ay += v.y * nm;
    }
    const float* bp = g ? biasB : biasA;
    float2 b2 = *(const float2*)(bp + 2 * lane);
    *(float2*)(R + (size_t)node * 128 + g * 64 + 2 * lane) =
        make_float2(ax + b2.x, ay + b2.y);
}

// ---------------- readout -----------------------------------------------------
__global__ __launch_bounds__(256) void readout_kernel(
    const float* __restrict__ Wr0, const float* __restrict__ br0,
    const float* __restrict__ Wr1, const float* __restrict__ br1,
    const float* __restrict__ Wr2, const float* __restrict__ br2,
    const float* __restrict__ Wr3, const float* __restrict__ br3,
    const float* __restrict__ w0, const float* __restrict__ w1,
    const float* __restrict__ w2, const float* __restrict__ w3,
    float* __restrict__ out, int n)
{
    int node = (blockIdx.x * blockDim.x + threadIdx.x) >> 5;
    if (node >= n) return;
    const int lane = threadIdx.x & 31;
    float W0 = w0[0], W1 = w1[0], W2 = w2[0], W3 = w3[0];
    float p = 0.f;
    {
        float2 r = *(const float2*)(g_R0 + (size_t)node * 64 + 2 * lane);
        float2 w = *(const float2*)(Wr0 + 2 * lane);
        p += W0 * (r.x * w.x + r.y * w.y);
    }
    {
        float4 r = *(const float4*)(g_R1 + (size_t)node * 128 + 4 * lane);
        float4 w = *(const float4*)(Wr1 + 4 * lane);
        p += W1 * (r.x * w.x + r.y * w.y + r.z * w.z + r.w * w.w);
    }
    {
        float4 r = *(const float4*)(g_R2 + (size_t)node * 128 + 4 * lane);
        float4 w = *(const float4*)(Wr2 + 4 * lane);
        p += W2 * (r.x * w.x + r.y * w.y + r.z * w.z + r.w * w.w);
    }
    {
        float4 r = *(const float4*)(g_R3 + (size_t)node * 128 + 4 * lane);
        float4 w = *(const float4*)(Wr3 + 4 * lane);
        p += W3 * (r.x * w.x + r.y * w.y + r.z * w.z + r.w * w.w);
    }
    #pragma unroll
    for (int o = 16; o; o >>= 1) p += __shfl_xor_sync(0xffffffffu, p, o);
    if (lane == 0)
        out[node] = p + W0 * br0[0] + W1 * br1[0] + W2 * br2[0] + W3 * br3[0];
}

// ---------------- launch ------------------------------------------------------
extern "C" void kernel_launch(void* const* d_in, const int* in_sizes, int n_in,
                              void* d_out, int out_size)
{
    const float* x    = (const float*)d_in[0];
    const int*   ei1  = (const int*)d_in[1];
    const int*   ei2  = (const int*)d_in[2];
    const float* W_in = (const float*)d_in[3];
    const float* b_in = (const float*)d_in[4];
    const float* W11  = (const float*)d_in[5];
    const float* b11  = (const float*)d_in[6];
    const float* W12  = (const float*)d_in[7];
    const float* b12  = (const float*)d_in[8];
    const float* W21  = (const float*)d_in[9];
    const float* b21  = (const float*)d_in[10];
    const float* W22  = (const float*)d_in[11];
    const float* b22  = (const float*)d_in[12];
    const float* W31  = (const float*)d_in[13];
    const float* b31  = (const float*)d_in[14];
    const float* W32  = (const float*)d_in[15];
    const float* b32  = (const float*)d_in[16];
    const float* Wr0  = (const float*)d_in[17];
    const float* br0  = (const float*)d_in[18];
    const float* Wr1  = (const float*)d_in[19];
    const float* br1  = (const float*)d_in[20];
    const float* Wr2  = (const float*)d_in[21];
    const float* br2  = (const float*)d_in[22];
    const float* Wr3  = (const float*)d_in[23];
    const float* br3  = (const float*)d_in[24];
    const float* w0   = (const float*)d_in[25];
    const float* w1   = (const float*)d_in[26];
    const float* w2   = (const float*)d_in[27];
    const float* w3   = (const float*)d_in[28];
    float* out = (float*)d_out;

    const int n = in_sizes[0] / 64;
    const int E = in_sizes[1] / 2;

    const int TB = 256;
    const int gE  = (E + TB - 1) / TB;
    const int gW2 = (2 * n * 32 + TB - 1) / TB;   // 2 graphs, warp-per-node
    const int gW  = (n * 32 + TB - 1) / TB;
    const int gG  = (n + 127) / 128;
    const int nch = (n + 4095) / 4096;

    float* R0 = nullptr; float* Y = nullptr; float* R1 = nullptr;
    float* R2 = nullptr; float* R3 = nullptr;
    cudaGetSymbolAddress((void**)&R0, g_R0);
    cudaGetSymbolAddress((void**)&Y,  g_y);
    cudaGetSymbolAddress((void**)&R1, g_R1);
    cudaGetSymbolAddress((void**)&R2, g_R2);
    cudaGetSymbolAddress((void**)&R3, g_R3);

    // --- CSR build for both graphs (parallel 3-phase scan) ---
    zero_cnt_kernel<<<(2 * n + TB - 1) / TB, TB>>>(n);
    hist_kernel<<<gE, TB>>>(ei1, ei2, E);
    scan_partial<<<2 * nch, TB>>>(n, nch);
    scan_bsum<<<1, 64>>>(n, nch);
    scan_final<<<2 * nch, TB>>>(n, nch);
    scatter_kernel<<<gE, TB>>>(ei1, ei2, E);

    // --- R0 = relu(x @ W_in + b_in) ---
    gemm2_kernel<64, false><<<gG, TB>>>(x, W_in, nullptr, b_in, R0, n);

    // --- layer 1: dual gemm + fused dual agg ---
    gemm2_kernel<64, true><<<gG, TB>>>(R0, W11, W12, nullptr, Y, n);
    agg2_kernel<<<gW2, TB>>>(Y, b11, b12, R1, n);

    // --- layer 2 ---
    gemm2_kernel<128, true><<<gG, TB>>>(R1, W21, W22, nullptr, Y, n);
    agg2_kernel<<<gW2, TB>>>(Y, b21, b22, R2, n);

    // --- layer 3 ---
    gemm2_kernel<128, true><<<gG, TB>>>(R2, W31, W32, nullptr, Y, n);
    agg2_kernel<<<gW2, TB>>>(Y, b31, b32, R3, n);

    // --- readout ---
    readout_kernel<<<gW, TB>>>(Wr0, br0, Wr1, br1, Wr2, br2, Wr3, br3,
                               w0, w1, w2, w3, out, n);
}

// round 8
// speedup vs baseline: 1.4942x; 1.0865x over previous
#include <cuda_runtime.h>
#include <cuda_fp16.h>
#include <cstdint>

#define NMAX 50000
#define EMAX 800000

// ---------------- scratch (device globals: no runtime allocation) -------------
__device__ int   g_cnt[2][NMAX];
__device__ int   g_offs[2][NMAX + 1];
__device__ int   g_cursor[2][NMAX];
__device__ int2  g_edge[2][EMAX];          // {row, __float_as_int(norm)} per CSR slot
__device__ float g_dinv[2][NMAX];
__device__ int   g_bsum[2][64];

__device__ float  g_R0[NMAX * 64];
__device__ __half g_yh[NMAX * 128];        // fp16 GEMM output consumed by aggregation
__device__ float  g_R1[NMAX * 128];
__device__ float  g_R2[NMAX * 128];
__device__ float  g_R3[NMAX * 128];

// ---------------- CSR build ---------------------------------------------------
__global__ void zero_cnt_kernel(int n) {
    int i = blockIdx.x * blockDim.x + threadIdx.x;
    if (i < 2 * n) (&g_cnt[0][0])[i] = 0;
}

__global__ void hist_kernel(const int* __restrict__ ei1, const int* __restrict__ ei2, int E) {
    int e = blockIdx.x * blockDim.x + threadIdx.x;
    if (e < E) {
        atomicAdd(&g_cnt[0][ei1[E + e]], 1);
        atomicAdd(&g_cnt[1][ei2[E + e]], 1);
    }
}

// phase 1: per-chunk (4096-elem) sums. grid = 2*nch blocks of 256.
__global__ void scan_partial(int n, int nch) {
    int b = blockIdx.x;
    int g = b / nch, c = b % nch;
    const int* __restrict__ cnt = g_cnt[g];
    int i0 = c * 4096 + threadIdx.x * 16;
    int tot = 0;
    #pragma unroll
    for (int j = 0; j < 16; j++) {
        int i = i0 + j;
        if (i < n) tot += cnt[i];
    }
    #pragma unroll
    for (int o = 16; o; o >>= 1) tot += __shfl_xor_sync(0xffffffffu, tot, o);
    __shared__ int ws[8];
    if ((threadIdx.x & 31) == 0) ws[threadIdx.x >> 5] = tot;
    __syncthreads();
    if (threadIdx.x == 0) {
        int s = 0;
        #pragma unroll
        for (int k = 0; k < 8; k++) s += ws[k];
        g_bsum[g][c] = s;
    }
}

// phase 2: exclusive scan of the <=32 chunk sums per graph; write offs[n]=total
__global__ void scan_bsum(int n, int nch) {
    int g = threadIdx.x >> 5;
    int lane = threadIdx.x & 31;
    if (g >= 2) return;
    int v = (lane < nch) ? g_bsum[g][lane] : 0;
    int s = v;
    #pragma unroll
    for (int o = 1; o < 32; o <<= 1) {
        int t = __shfl_up_sync(0xffffffffu, s, o);
        if (lane >= o) s += t;
    }
    if (lane < nch) g_bsum[g][lane] = s - v;  // exclusive
    if (lane == 31) g_offs[g][n] = s;         // total
}

// phase 3: per-chunk rescan -> offs, cursor; also dinv. grid = 2*nch blocks.
__global__ void scan_final(int n, int nch) {
    int b = blockIdx.x;
    int g = b / nch, c = b % nch;
    const int* __restrict__ cnt = g_cnt[g];
    int* __restrict__ offs = g_offs[g];
    int* __restrict__ cur  = g_cursor[g];
    float* __restrict__ dinv = g_dinv[g];
    int base = g_bsum[g][c];
    int i0 = c * 4096 + threadIdx.x * 16;

    int v[16];
    int tsum = 0;
    #pragma unroll
    for (int j = 0; j < 16; j++) {
        int i = i0 + j;
        v[j] = (i < n) ? cnt[i] : 0;
        tsum += v[j];
    }
    const int lane = threadIdx.x & 31;
    const int wid  = threadIdx.x >> 5;
    int s = tsum;
    #pragma unroll
    for (int o = 1; o < 32; o <<= 1) {
        int t = __shfl_up_sync(0xffffffffu, s, o);
        if (lane >= o) s += t;
    }
    __shared__ int ws[8];
    if (lane == 31) ws[wid] = s;
    __syncthreads();
    int woff = 0;
    if (wid > 0) {
        #pragma unroll
        for (int k = 0; k < 7; k++) if (k < wid) woff += ws[k];
    }
    int run = base + woff + (s - tsum);
    #pragma unroll
    for (int j = 0; j < 16; j++) {
        int i = i0 + j;
        if (i < n) {
            offs[i] = run;
            cur[i]  = run;
            dinv[i] = v[j] > 0 ? rsqrtf((float)v[j]) : 0.f;
        }
        run += v[j];
    }
}

// scatter edges into CSR with the full symmetric norm precomputed per slot
__global__ void scatter_kernel(const int* __restrict__ ei1, const int* __restrict__ ei2, int E) {
    int e = blockIdx.x * blockDim.x + threadIdx.x;
    if (e < E) {
        int r = ei1[e], c = ei1[E + e];
        int p = atomicAdd(&g_cursor[0][c], 1);
        float nm = g_dinv[0][c] * g_dinv[0][r];
        g_edge[0][p] = make_int2(r, __float_as_int(nm));
        r = ei2[e]; c = ei2[E + e];
        p = atomicAdd(&g_cursor[1][c], 1);
        nm = g_dinv[1][c] * g_dinv[1][r];
        g_edge[1][p] = make_int2(r, __float_as_int(nm));
    }
}

// ---------------- GEMM --------------------------------------------------------
// Tile 128 rows. DUAL: two weight matrices [KDIM,64] -> Yh[M,128] fp16 (Ya|Yb).
// !DUAL: single [KDIM,64] -> Yf[M,64] fp32 with bias+relu (for R0).
template<int KDIM, bool DUAL>
__global__ __launch_bounds__(256, 2) void gemm2_kernel(
    const float* __restrict__ X, const float* __restrict__ Wa,
    const float* __restrict__ Wb, const float* __restrict__ bias,
    float* __restrict__ Yf, __half* __restrict__ Yh, int M)
{
    constexpr int NB = DUAL ? 128 : 64;
    __shared__ float Xs[128][36];   // k-tile 32, pad to 36 floats
    __shared__ float Ws[32][NB];

    const int row0 = blockIdx.x * 128;
    const int tx = threadIdx.x & 15;
    const int ty = threadIdx.x >> 4;
    const int txc = tx * 4;
    const int tyr = ty * 4;

    float accTA[4][4] = {}, accBA[4][4] = {};
    float accTB[4][4] = {}, accBB[4][4] = {};

    for (int kt = 0; kt < KDIM; kt += 32) {
        #pragma unroll
        for (int p = 0; p < 4; p++) {
            int f = threadIdx.x + p * 256;       // 0..1023
            int r = f >> 3, kq = (f & 7) * 4;
            float4 v = make_float4(0.f, 0.f, 0.f, 0.f);
            if (row0 + r < M)
                v = *(const float4*)(X + (size_t)(row0 + r) * KDIM + kt + kq);
            *(float4*)&Xs[r][kq] = v;
        }
        if (DUAL) {
            #pragma unroll
            for (int p = 0; p < 4; p++) {
                int f = threadIdx.x + p * 256;   // 0..1023
                int k = f >> 5, cq = (f & 31) * 4;
                float4 v = (cq < 64)
                    ? *(const float4*)(Wa + (size_t)(kt + k) * 64 + cq)
                    : *(const float4*)(Wb + (size_t)(kt + k) * 64 + (cq - 64));
                *(float4*)&Ws[k][cq] = v;
            }
        } else {
            #pragma unroll
            for (int p = 0; p < 2; p++) {
                int f = threadIdx.x + p * 256;   // 0..511
                int k = f >> 4, cq = (f & 15) * 4;
                *(float4*)&Ws[k][cq] = *(const float4*)(Wa + (size_t)(kt + k) * 64 + cq);
            }
        }
        __syncthreads();

        #pragma unroll 4
        for (int k = 0; k < 32; k++) {
            float4 bA = *(const float4*)&Ws[k][txc];
            float4 bB;
            if (DUAL) bB = *(const float4*)&Ws[k][64 + txc];
            #pragma unroll
            for (int r = 0; r < 4; r++) {
                float aT = Xs[tyr + r][k];
                float aB = Xs[64 + tyr + r][k];
                accTA[r][0] += aT * bA.x; accTA[r][1] += aT * bA.y;
                accTA[r][2] += aT * bA.z; accTA[r][3] += aT * bA.w;
                accBA[r][0] += aB * bA.x; accBA[r][1] += aB * bA.y;
                accBA[r][2] += aB * bA.z; accBA[r][3] += aB * bA.w;
                if (DUAL) {
                    accTB[r][0] += aT * bB.x; accTB[r][1] += aT * bB.y;
                    accTB[r][2] += aT * bB.z; accTB[r][3] += aT * bB.w;
                    accBB[r][0] += aB * bB.x; accBB[r][1] += aB * bB.y;
                    accBB[r][2] += aB * bB.z; accBB[r][3] += aB * bB.w;
                }
            }
        }
        __syncthreads();
    }

    if (DUAL) {
        #pragma unroll
        for (int r = 0; r < 4; r++) {
            int gT = row0 + tyr + r;
            if (gT < M) {
                __half* p = Yh + (size_t)gT * 128;
                *(__half2*)(p + txc)      = __floats2half2_rn(accTA[r][0], accTA[r][1]);
                *(__half2*)(p + txc + 2)  = __floats2half2_rn(accTA[r][2], accTA[r][3]);
                *(__half2*)(p + 64 + txc)     = __floats2half2_rn(accTB[r][0], accTB[r][1]);
                *(__half2*)(p + 64 + txc + 2) = __floats2half2_rn(accTB[r][2], accTB[r][3]);
            }
            int gB = row0 + 64 + tyr + r;
            if (gB < M) {
                __half* p = Yh + (size_t)gB * 128;
                *(__half2*)(p + txc)      = __floats2half2_rn(accBA[r][0], accBA[r][1]);
                *(__half2*)(p + txc + 2)  = __floats2half2_rn(accBA[r][2], accBA[r][3]);
                *(__half2*)(p + 64 + txc)     = __floats2half2_rn(accBB[r][0], accBB[r][1]);
                *(__half2*)(p + 64 + txc + 2) = __floats2half2_rn(accBB[r][2], accBB[r][3]);
            }
        }
    } else {
        float4 bb = *(const float4*)(bias + txc);
        #pragma unroll
        for (int r = 0; r < 4; r++) {
            int gT = row0 + tyr + r;
            if (gT < M) {
                float4 o = make_float4(fmaxf(accTA[r][0] + bb.x, 0.f),
                                       fmaxf(accTA[r][1] + bb.y, 0.f),
                                       fmaxf(accTA[r][2] + bb.z, 0.f),
                                       fmaxf(accTA[r][3] + bb.w, 0.f));
                *(float4*)(Yf + (size_t)gT * 64 + txc) = o;
            }
            int gB = row0 + 64 + tyr + r;
            if (gB < M) {
                float4 o = make_float4(fmaxf(accBA[r][0] + bb.x, 0.f),
                                       fmaxf(accBA[r][1] + bb.y, 0.f),
                                       fmaxf(accBA[r][2] + bb.z, 0.f),
                                       fmaxf(accBA[r][3] + bb.w, 0.f));
                *(float4*)(Yf + (size_t)gB * 64 + txc) = o;
            }
        }
    }
}

// ---------------- fused dual-graph aggregation (fp16 gather, fp32 accum) ------
// y: [M,128] fp16 (Ya|Yb). Warp w<n: graph 0 cols 0-63 -> R[:,0:64];
// w>=n: graph 1 cols 64-127 -> R[:,64:128]. One warp/node, half2 per lane.
__global__ __launch_bounds__(256) void agg2_kernel(
    const __half* __restrict__ y,
    const float* __restrict__ biasA, const float* __restrict__ biasB,
    float* __restrict__ R, int n)
{
    int w = (blockIdx.x * blockDim.x + threadIdx.x) >> 5;
    if (w >= 2 * n) return;
    const int g = (w >= n) ? 1 : 0;
    const int node = w - g * n;
    const int lane = threadIdx.x & 31;

    const int* __restrict__ offs = g_offs[g];
    const int2* __restrict__ ed = g_edge[g];
    const __half* __restrict__ ys = y + g * 64 + 2 * lane;

    int s = offs[node], e = offs[node + 1];
    float ax = 0.f, ay = 0.f;
    int i = s;
    for (; i + 4 <= e; i += 4) {
        int2 e0 = ed[i], e1 = ed[i + 1], e2 = ed[i + 2], e3 = ed[i + 3];
        float2 v0 = __half22float2(*(const __half2*)(ys + (size_t)e0.x * 128));
        float2 v1 = __half22float2(*(const __half2*)(ys + (size_t)e1.x * 128));
        float2 v2 = __half22float2(*(const __half2*)(ys + (size_t)e2.x * 128));
        float2 v3 = __half22float2(*(const __half2*)(ys + (size_t)e3.x * 128));
        float n0 = __int_as_float(e0.y), n1 = __int_as_float(e1.y);
        float n2 = __int_as_float(e2.y), n3 = __int_as_float(e3.y);
        ax += v0.x * n0 + v1.x * n1 + v2.x * n2 + v3.x * n3;
        ay += v0.y * n0 + v1.y * n1 + v2.y * n2 + v3.y * n3;
    }
    for (; i < e; i++) {
        int2 ee = ed[i];
        float2 v = __half22float2(*(const __half2*)(ys + (size_t)ee.x * 128));
        float nm = __int_as_float(ee.y);
        ax += v.x * nm;
        ay += v.y * nm;
    }
    const float* bp = g ? biasB : biasA;
    float2 b2 = *(const float2*)(bp + 2 * lane);
    *(float2*)(R + (size_t)node * 128 + g * 64 + 2 * lane) =
        make_float2(ax + b2.x, ay + b2.y);
}

// ---------------- readout -----------------------------------------------------
__global__ __launch_bounds__(256) void readout_kernel(
    const float* __restrict__ Wr0, const float* __restrict__ br0,
    const float* __restrict__ Wr1, const float* __restrict__ br1,
    const float* __restrict__ Wr2, const float* __restrict__ br2,
    const float* __restrict__ Wr3, const float* __restrict__ br3,
    const float* __restrict__ w0, const float* __restrict__ w1,
    const float* __restrict__ w2, const float* __restrict__ w3,
    float* __restrict__ out, int n)
{
    int node = (blockIdx.x * blockDim.x + threadIdx.x) >> 5;
    if (node >= n) return;
    const int lane = threadIdx.x & 31;
    float W0 = w0[0], W1 = w1[0], W2 = w2[0], W3 = w3[0];
    float p = 0.f;
    {
        float2 r = *(const float2*)(g_R0 + (size_t)node * 64 + 2 * lane);
        float2 w = *(const float2*)(Wr0 + 2 * lane);
        p += W0 * (r.x * w.x + r.y * w.y);
    }
    {
        float4 r = *(const float4*)(g_R1 + (size_t)node * 128 + 4 * lane);
        float4 w = *(const float4*)(Wr1 + 4 * lane);
        p += W1 * (r.x * w.x + r.y * w.y + r.z * w.z + r.w * w.w);
    }
    {
        float4 r = *(const float4*)(g_R2 + (size_t)node * 128 + 4 * lane);
        float4 w = *(const float4*)(Wr2 + 4 * lane);
        p += W2 * (r.x * w.x + r.y * w.y + r.z * w.z + r.w * w.w);
    }
    {
        float4 r = *(const float4*)(g_R3 + (size_t)node * 128 + 4 * lane);
        float4 w = *(const float4*)(Wr3 + 4 * lane);
        p += W3 * (r.x * w.x + r.y * w.y + r.z * w.z + r.w * w.w);
    }
    #pragma unroll
    for (int o = 16; o; o >>= 1) p += __shfl_xor_sync(0xffffffffu, p, o);
    if (lane == 0)
        out[node] = p + W0 * br0[0] + W1 * br1[0] + W2 * br2[0] + W3 * br3[0];
}

// ---------------- launch ------------------------------------------------------
extern "C" void kernel_launch(void* const* d_in, const int* in_sizes, int n_in,
                              void* d_out, int out_size)
{
    const float* x    = (const float*)d_in[0];
    const int*   ei1  = (const int*)d_in[1];
    const int*   ei2  = (const int*)d_in[2];
    const float* W_in = (const float*)d_in[3];
    const float* b_in = (const float*)d_in[4];
    const float* W11  = (const float*)d_in[5];
    const float* b11  = (const float*)d_in[6];
    const float* W12  = (const float*)d_in[7];
    const float* b12  = (const float*)d_in[8];
    const float* W21  = (const float*)d_in[9];
    const float* b21  = (const float*)d_in[10];
    const float* W22  = (const float*)d_in[11];
    const float* b22  = (const float*)d_in[12];
    const float* W31  = (const float*)d_in[13];
    const float* b31  = (const float*)d_in[14];
    const float* W32  = (const float*)d_in[15];
    const float* b32  = (const float*)d_in[16];
    const float* Wr0  = (const float*)d_in[17];
    const float* br0  = (const float*)d_in[18];
    const float* Wr1  = (const float*)d_in[19];
    const float* br1  = (const float*)d_in[20];
    const float* Wr2  = (const float*)d_in[21];
    const float* br2  = (const float*)d_in[22];
    const float* Wr3  = (const float*)d_in[23];
    const float* br3  = (const float*)d_in[24];
    const float* w0   = (const float*)d_in[25];
    const float* w1   = (const float*)d_in[26];
    const float* w2   = (const float*)d_in[27];
    const float* w3   = (const float*)d_in[28];
    float* out = (float*)d_out;

    const int n = in_sizes[0] / 64;
    const int E = in_sizes[1] / 2;

    const int TB = 256;
    const int gE  = (E + TB - 1) / TB;
    const int gW2 = (2 * n * 32 + TB - 1) / TB;   // 2 graphs, warp-per-node
    const int gW  = (n * 32 + TB - 1) / TB;
    const int gG  = (n + 127) / 128;
    const int nch = (n + 4095) / 4096;

    float* R0 = nullptr; __half* Yh = nullptr;
    float* R1 = nullptr; float* R2 = nullptr; float* R3 = nullptr;
    cudaGetSymbolAddress((void**)&R0, g_R0);
    cudaGetSymbolAddress((void**)&Yh, g_yh);
    cudaGetSymbolAddress((void**)&R1, g_R1);
    cudaGetSymbolAddress((void**)&R2, g_R2);
    cudaGetSymbolAddress((void**)&R3, g_R3);

    // --- CSR build for both graphs (parallel 3-phase scan) ---
    zero_cnt_kernel<<<(2 * n + TB - 1) / TB, TB>>>(n);
    hist_kernel<<<gE, TB>>>(ei1, ei2, E);
    scan_partial<<<2 * nch, TB>>>(n, nch);
    scan_bsum<<<1, 64>>>(n, nch);
    scan_final<<<2 * nch, TB>>>(n, nch);
    scatter_kernel<<<gE, TB>>>(ei1, ei2, E);

    // --- R0 = relu(x @ W_in + b_in) ---
    gemm2_kernel<64, false><<<gG, TB>>>(x, W_in, nullptr, b_in, R0, nullptr, n);

    // --- layer 1: dual gemm (fp16 out) + fused dual agg ---
    gemm2_kernel<64, true><<<gG, TB>>>(R0, W11, W12, nullptr, nullptr, Yh, n);
    agg2_kernel<<<gW2, TB>>>(Yh, b11, b12, R1, n);

    // --- layer 2 ---
    gemm2_kernel<128, true><<<gG, TB>>>(R1, W21, W22, nullptr, nullptr, Yh, n);
    agg2_kernel<<<gW2, TB>>>(Yh, b21, b22, R2, n);

    // --- layer 3 ---
    gemm2_kernel<128, true><<<gG, TB>>>(R2, W31, W32, nullptr, nullptr, Yh, n);
    agg2_kernel<<<gW2, TB>>>(Yh, b31, b32, R3, n);

    // --- readout ---
    readout_kernel<<<gW, TB>>>(Wr0, br0, Wr1, br1, Wr2, br2, Wr3, br3,
                               w0, w1, w2, w3, out, n);
}

// round 9
// speedup vs baseline: 2.0321x; 1.3600x over previous
#include <cuda_runtime.h>
#include <cuda_fp16.h>
#include <cstdint>

#define NMAX 50000
#define EMAX 800000

// ---------------- scratch (device globals: no runtime allocation) -------------
__device__ int   g_cnt[2][NMAX];
__device__ int   g_offs[2][NMAX + 1];
__device__ int   g_cursor[2][NMAX];
__device__ int2  g_edge[2][EMAX];          // {row, __float_as_int(norm)} per CSR slot
__device__ float g_dinv[2][NMAX];
__device__ int   g_bsum[2][64];

__device__ float  g_R0[NMAX * 64];
__device__ __half g_R0h[NMAX * 64];        // fp16 copy of R0 (GEMM input)
__device__ __half g_yh[NMAX * 128];        // fp16 GEMM output consumed by aggregation
__device__ __half g_Rh[NMAX * 128];        // fp16 copy of latest R (GEMM input)
__device__ float  g_R1[NMAX * 128];
__device__ float  g_R2[NMAX * 128];
__device__ float  g_R3[NMAX * 128];

// ---------------- CSR build ---------------------------------------------------
__global__ void zero_cnt_kernel(int n) {
    int i = blockIdx.x * blockDim.x + threadIdx.x;
    if (i < 2 * n) (&g_cnt[0][0])[i] = 0;
}

__global__ void hist_kernel(const int* __restrict__ ei1, const int* __restrict__ ei2, int E) {
    int e = blockIdx.x * blockDim.x + threadIdx.x;
    if (e < E) {
        atomicAdd(&g_cnt[0][ei1[E + e]], 1);
        atomicAdd(&g_cnt[1][ei2[E + e]], 1);
    }
}

__global__ void scan_partial(int n, int nch) {
    int b = blockIdx.x;
    int g = b / nch, c = b % nch;
    const int* __restrict__ cnt = g_cnt[g];
    int i0 = c * 4096 + threadIdx.x * 16;
    int tot = 0;
    #pragma unroll
    for (int j = 0; j < 16; j++) {
        int i = i0 + j;
        if (i < n) tot += cnt[i];
    }
    #pragma unroll
    for (int o = 16; o; o >>= 1) tot += __shfl_xor_sync(0xffffffffu, tot, o);
    __shared__ int ws[8];
    if ((threadIdx.x & 31) == 0) ws[threadIdx.x >> 5] = tot;
    __syncthreads();
    if (threadIdx.x == 0) {
        int s = 0;
        #pragma unroll
        for (int k = 0; k < 8; k++) s += ws[k];
        g_bsum[g][c] = s;
    }
}

__global__ void scan_bsum(int n, int nch) {
    int g = threadIdx.x >> 5;
    int lane = threadIdx.x & 31;
    if (g >= 2) return;
    int v = (lane < nch) ? g_bsum[g][lane] : 0;
    int s = v;
    #pragma unroll
    for (int o = 1; o < 32; o <<= 1) {
        int t = __shfl_up_sync(0xffffffffu, s, o);
        if (lane >= o) s += t;
    }
    if (lane < nch) g_bsum[g][lane] = s - v;
    if (lane == 31) g_offs[g][n] = s;
}

__global__ void scan_final(int n, int nch) {
    int b = blockIdx.x;
    int g = b / nch, c = b % nch;
    const int* __restrict__ cnt = g_cnt[g];
    int* __restrict__ offs = g_offs[g];
    int* __restrict__ cur  = g_cursor[g];
    float* __restrict__ dinv = g_dinv[g];
    int base = g_bsum[g][c];
    int i0 = c * 4096 + threadIdx.x * 16;

    int v[16];
    int tsum = 0;
    #pragma unroll
    for (int j = 0; j < 16; j++) {
        int i = i0 + j;
        v[j] = (i < n) ? cnt[i] : 0;
        tsum += v[j];
    }
    const int lane = threadIdx.x & 31;
    const int wid  = threadIdx.x >> 5;
    int s = tsum;
    #pragma unroll
    for (int o = 1; o < 32; o <<= 1) {
        int t = __shfl_up_sync(0xffffffffu, s, o);
        if (lane >= o) s += t;
    }
    __shared__ int ws[8];
    if (lane == 31) ws[wid] = s;
    __syncthreads();
    int woff = 0;
    if (wid > 0) {
        #pragma unroll
        for (int k = 0; k < 7; k++) if (k < wid) woff += ws[k];
    }
    int run = base + woff + (s - tsum);
    #pragma unroll
    for (int j = 0; j < 16; j++) {
        int i = i0 + j;
        if (i < n) {
            offs[i] = run;
            cur[i]  = run;
            dinv[i] = v[j] > 0 ? rsqrtf((float)v[j]) : 0.f;
        }
        run += v[j];
    }
}

__global__ void scatter_kernel(const int* __restrict__ ei1, const int* __restrict__ ei2, int E) {
    int e = blockIdx.x * blockDim.x + threadIdx.x;
    if (e < E) {
        int r = ei1[e], c = ei1[E + e];
        int p = atomicAdd(&g_cursor[0][c], 1);
        float nm = g_dinv[0][c] * g_dinv[0][r];
        g_edge[0][p] = make_int2(r, __float_as_int(nm));
        r = ei2[e]; c = ei2[E + e];
        p = atomicAdd(&g_cursor[1][c], 1);
        nm = g_dinv[1][c] * g_dinv[1][r];
        g_edge[1][p] = make_int2(r, __float_as_int(nm));
    }
}

// ---------------- tensor-core GEMM -------------------------------------------
__device__ __forceinline__ uint32_t smem_u32(const void* p) {
    uint32_t a;
    asm volatile("{ .reg .u64 t; cvta.to.shared.u64 t, %1; cvt.u32.u64 %0, t; }"
                 : "=r"(a) : "l"(p));
    return a;
}

__device__ __forceinline__ void mma16816(float* c, const uint32_t* a, const uint32_t* b) {
    asm volatile(
        "mma.sync.aligned.m16n8k16.row.col.f32.f16.f16.f32 "
        "{%0,%1,%2,%3},{%4,%5,%6,%7},{%8,%9},{%0,%1,%2,%3};"
        : "+f"(c[0]), "+f"(c[1]), "+f"(c[2]), "+f"(c[3])
        : "r"(a[0]), "r"(a[1]), "r"(a[2]), "r"(a[3]), "r"(b[0]), "r"(b[1]));
}

// C[M,NB] = X[M,KDIM] @ [Wa|Wb][KDIM,NB], fp16 inputs, fp32 accum.
// DUAL: NB=128 (Wa|Wb), out fp16 Yh[M,128].
// !DUAL: NB=64 (Wa), bias+relu, out fp32 Yf[M,64] + fp16 Yh[M,64].
// XHALF: X is fp16 [M,KDIM]; else fp32 (converted at load).
template<int KDIM, bool DUAL, bool XHALF>
__global__ __launch_bounds__(256) void mma_gemm_kernel(
    const void* __restrict__ Xv, const float* __restrict__ Wa,
    const float* __restrict__ Wb, const float* __restrict__ bias,
    float* __restrict__ Yf, __half* __restrict__ Yh, int M)
{
    constexpr int NB = DUAL ? 128 : 64;
    constexpr int KP = KDIM + 8;   // padded X stride (halves) — 16B granularity rotation
    constexpr int NP = NB + 8;     // padded W stride
    constexpr int NT = (NB / 2) / 8;     // n-tiles per warp (8 or 4)
    constexpr int KT = KDIM / 16;        // k-steps

    extern __shared__ __align__(16) char dynsmem[];
    __half* Xs = (__half*)dynsmem;
    __half* Ws = Xs + 128 * KP;

    const int tid = threadIdx.x;
    const int row0 = blockIdx.x * 128;

    // ---- load X tile (128 x KDIM) ----
    if (XHALF) {
        const __half* Xh = (const __half*)Xv;
        constexpr int XU = 128 * KDIM / 8;          // uint4 units (8 halves)
        #pragma unroll
        for (int u = tid; u < XU; u += 256) {
            int r = u / (KDIM / 8), q = u % (KDIM / 8);
            uint4 v = make_uint4(0u, 0u, 0u, 0u);
            if (row0 + r < M)
                v = *(const uint4*)(Xh + (size_t)(row0 + r) * KDIM + q * 8);
            *(uint4*)&Xs[r * KP + q * 8] = v;
        }
    } else {
        const float* Xf = (const float*)Xv;
        constexpr int XU = 128 * KDIM / 4;          // float4 units
        #pragma unroll
        for (int u = tid; u < XU; u += 256) {
            int r = u / (KDIM / 4), q = u % (KDIM / 4);
            float4 v = make_float4(0.f, 0.f, 0.f, 0.f);
            if (row0 + r < M)
                v = *(const float4*)(Xf + (size_t)(row0 + r) * KDIM + q * 4);
            union { __half2 h[2]; uint2 u2; } t;
            t.h[0] = __floats2half2_rn(v.x, v.y);
            t.h[1] = __floats2half2_rn(v.z, v.w);
            *(uint2*)&Xs[r * KP + q * 4] = t.u2;
        }
    }
    // ---- load W tile(s) (KDIM x NB), fp32 -> fp16 ----
    {
        constexpr int WU = KDIM * 16 * (DUAL ? 2 : 1);  // float4 units
        #pragma unroll
        for (int u = tid; u < WU; u += 256) {
            int mat = DUAL ? (u >= KDIM * 16 ? 1 : 0) : 0;
            int v = u - mat * KDIM * 16;
            int k = v >> 4, q = v & 15;
            float4 w = *(const float4*)((mat ? Wb : Wa) + (size_t)k * 64 + q * 4);
            union { __half2 h[2]; uint2 u2; } t;
            t.h[0] = __floats2half2_rn(w.x, w.y);
            t.h[1] = __floats2half2_rn(w.z, w.w);
            *(uint2*)&Ws[k * NP + mat * 64 + q * 4] = t.u2;
        }
    }
    __syncthreads();

    const int wid = tid >> 5, lane = tid & 31;
    const int wm = (wid & 3) * 32;               // warp row offset (0..96)
    const int wn = (wid >> 2) * (NB / 2);        // warp col offset
    const uint32_t xs0 = smem_u32(Xs);
    const uint32_t ws0 = smem_u32(Ws);

    float acc[2][NT][4];
    #pragma unroll
    for (int mt = 0; mt < 2; mt++)
        #pragma unroll
        for (int nt = 0; nt < NT; nt++)
            #pragma unroll
            for (int j = 0; j < 4; j++) acc[mt][nt][j] = 0.f;

    const int lr = lane & 15;       // ldmatrix row select
    const int lc = (lane >> 4) * 8; // ldmatrix col-half select

    #pragma unroll
    for (int kk = 0; kk < KT; kk++) {
        uint32_t a[2][4];
        #pragma unroll
        for (int mt = 0; mt < 2; mt++) {
            uint32_t addr = xs0 + ((wm + mt * 16 + lr) * KP + kk * 16 + lc) * 2;
            asm volatile("ldmatrix.sync.aligned.m8n8.x4.shared.b16 {%0,%1,%2,%3},[%4];"
                         : "=r"(a[mt][0]), "=r"(a[mt][1]), "=r"(a[mt][2]), "=r"(a[mt][3])
                         : "r"(addr));
        }
        uint32_t b[NT][2];
        #pragma unroll
        for (int bt = 0; bt < NT / 2; bt++) {
            uint32_t addr = ws0 + ((kk * 16 + lr) * NP + wn + bt * 16 + lc) * 2;
            asm volatile("ldmatrix.sync.aligned.m8n8.x4.trans.shared.b16 {%0,%1,%2,%3},[%4];"
                         : "=r"(b[2 * bt][0]), "=r"(b[2 * bt][1]),
                           "=r"(b[2 * bt + 1][0]), "=r"(b[2 * bt + 1][1])
                         : "r"(addr));
        }
        #pragma unroll
        for (int mt = 0; mt < 2; mt++)
            #pragma unroll
            for (int nt = 0; nt < NT; nt++)
                mma16816(acc[mt][nt], a[mt], b[nt]);
    }

    // ---- epilogue ----
    const int gid = lane >> 2;          // row within 8
    const int t4  = (lane & 3) * 2;     // col pair
    if (DUAL) {
        #pragma unroll
        for (int mt = 0; mt < 2; mt++) {
            #pragma unroll
            for (int nt = 0; nt < NT; nt++) {
                int col = wn + nt * 8 + t4;
                int r0 = row0 + wm + mt * 16 + gid;
                if (r0 < M)
                    *(__half2*)&Yh[(size_t)r0 * 128 + col] =
                        __floats2half2_rn(acc[mt][nt][0], acc[mt][nt][1]);
                int r1 = r0 + 8;
                if (r1 < M)
                    *(__half2*)&Yh[(size_t)r1 * 128 + col] =
                        __floats2half2_rn(acc[mt][nt][2], acc[mt][nt][3]);
            }
        }
    } else {
        #pragma unroll
        for (int mt = 0; mt < 2; mt++) {
            #pragma unroll
            for (int nt = 0; nt < NT; nt++) {
                int col = wn + nt * 8 + t4;
                float b0 = __ldg(bias + col), b1 = __ldg(bias + col + 1);
                int r0 = row0 + wm + mt * 16 + gid;
                if (r0 < M) {
                    float o0 = fmaxf(acc[mt][nt][0] + b0, 0.f);
                    float o1 = fmaxf(acc[mt][nt][1] + b1, 0.f);
                    *(float2*)&Yf[(size_t)r0 * 64 + col] = make_float2(o0, o1);
                    *(__half2*)&Yh[(size_t)r0 * 64 + col] = __floats2half2_rn(o0, o1);
                }
                int r1 = r0 + 8;
                if (r1 < M) {
                    float o0 = fmaxf(acc[mt][nt][2] + b0, 0.f);
                    float o1 = fmaxf(acc[mt][nt][3] + b1, 0.f);
                    *(float2*)&Yf[(size_t)r1 * 64 + col] = make_float2(o0, o1);
                    *(__half2*)&Yh[(size_t)r1 * 64 + col] = __floats2half2_rn(o0, o1);
                }
            }
        }
    }
}

// ---------------- fused dual-graph aggregation (fp16 gather, fp32 accum) ------
__global__ __launch_bounds__(256) void agg2_kernel(
    const __half* __restrict__ y,
    const float* __restrict__ biasA, const float* __restrict__ biasB,
    float* __restrict__ R, __half* __restrict__ Rh, int n)
{
    int w = (blockIdx.x * blockDim.x + threadIdx.x) >> 5;
    if (w >= 2 * n) return;
    const int g = (w >= n) ? 1 : 0;
    const int node = w - g * n;
    const int lane = threadIdx.x & 31;

    const int* __restrict__ offs = g_offs[g];
    const int2* __restrict__ ed = g_edge[g];
    const __half* __restrict__ ys = y + g * 64 + 2 * lane;

    int s = offs[node], e = offs[node + 1];
    float ax = 0.f, ay = 0.f;
    int i = s;
    for (; i + 4 <= e; i += 4) {
        int2 e0 = ed[i], e1 = ed[i + 1], e2 = ed[i + 2], e3 = ed[i + 3];
        float2 v0 = __half22float2(*(const __half2*)(ys + (size_t)e0.x * 128));
        float2 v1 = __half22float2(*(const __half2*)(ys + (size_t)e1.x * 128));
        float2 v2 = __half22float2(*(const __half2*)(ys + (size_t)e2.x * 128));
        float2 v3 = __half22float2(*(const __half2*)(ys + (size_t)e3.x * 128));
        float n0 = __int_as_float(e0.y), n1 = __int_as_float(e1.y);
        float n2 = __int_as_float(e2.y), n3 = __int_as_float(e3.y);
        ax += v0.x * n0 + v1.x * n1 + v2.x * n2 + v3.x * n3;
        ay += v0.y * n0 + v1.y * n1 + v2.y * n2 + v3.y * n3;
    }
    for (; i < e; i++) {
        int2 ee = ed[i];
        float2 v = __half22float2(*(const __half2*)(ys + (size_t)ee.x * 128));
        float nm = __int_as_float(ee.y);
        ax += v.x * nm;
        ay += v.y * nm;
    }
    const float* bp = g ? biasB : biasA;
    float2 b2 = *(const float2*)(bp + 2 * lane);
    float2 o = make_float2(ax + b2.x, ay + b2.y);
    size_t off = (size_t)node * 128 + g * 64 + 2 * lane;
    *(float2*)(R + off) = o;
    if (Rh) *(__half2*)(Rh + off) = __floats2half2_rn(o.x, o.y);
}

// ---------------- readout -----------------------------------------------------
__global__ __launch_bounds__(256) void readout_kernel(
    const float* __restrict__ Wr0, const float* __restrict__ br0,
    const float* __restrict__ Wr1, const float* __restrict__ br1,
    const float* __restrict__ Wr2, const float* __restrict__ br2,
    const float* __restrict__ Wr3, const float* __restrict__ br3,
    const float* __restrict__ w0, const float* __restrict__ w1,
    const float* __restrict__ w2, const float* __restrict__ w3,
    float* __restrict__ out, int n)
{
    int node = (blockIdx.x * blockDim.x + threadIdx.x) >> 5;
    if (node >= n) return;
    const int lane = threadIdx.x & 31;
    float W0 = w0[0], W1 = w1[0], W2 = w2[0], W3 = w3[0];
    float p = 0.f;
    {
        float2 r = *(const float2*)(g_R0 + (size_t)node * 64 + 2 * lane);
        float2 w = *(const float2*)(Wr0 + 2 * lane);
        p += W0 * (r.x * w.x + r.y * w.y);
    }
    {
        float4 r = *(const float4*)(g_R1 + (size_t)node * 128 + 4 * lane);
        float4 w = *(const float4*)(Wr1 + 4 * lane);
        p += W1 * (r.x * w.x + r.y * w.y + r.z * w.z + r.w * w.w);
    }
    {
        float4 r = *(const float4*)(g_R2 + (size_t)node * 128 + 4 * lane);
        float4 w = *(const float4*)(Wr2 + 4 * lane);
        p += W2 * (r.x * w.x + r.y * w.y + r.z * w.z + r.w * w.w);
    }
    {
        float4 r = *(const float4*)(g_R3 + (size_t)node * 128 + 4 * lane);
        float4 w = *(const float4*)(Wr3 + 4 * lane);
        p += W3 * (r.x * w.x + r.y * w.y + r.z * w.z + r.w * w.w);
    }
    #pragma unroll
    for (int o = 16; o; o >>= 1) p += __shfl_xor_sync(0xffffffffu, p, o);
    if (lane == 0)
        out[node] = p + W0 * br0[0] + W1 * br1[0] + W2 * br2[0] + W3 * br3[0];
}

// ---------------- launch ------------------------------------------------------
extern "C" void kernel_launch(void* const* d_in, const int* in_sizes, int n_in,
                              void* d_out, int out_size)
{
    const float* x    = (const float*)d_in[0];
    const int*   ei1  = (const int*)d_in[1];
    const int*   ei2  = (const int*)d_in[2];
    const float* W_in = (const float*)d_in[3];
    const float* b_in = (const float*)d_in[4];
    const float* W11  = (const float*)d_in[5];
    const float* b11  = (const float*)d_in[6];
    const float* W12  = (const float*)d_in[7];
    const float* b12  = (const float*)d_in[8];
    const float* W21  = (const float*)d_in[9];
    const float* b21  = (const float*)d_in[10];
    const float* W22  = (const float*)d_in[11];
    const float* b22  = (const float*)d_in[12];
    const float* W31  = (const float*)d_in[13];
    const float* b31  = (const float*)d_in[14];
    const float* W32  = (const float*)d_in[15];
    const float* b32  = (const float*)d_in[16];
    const float* Wr0  = (const float*)d_in[17];
    const float* br0  = (const float*)d_in[18];
    const float* Wr1  = (const float*)d_in[19];
    const float* br1  = (const float*)d_in[20];
    const float* Wr2  = (const float*)d_in[21];
    const float* br2  = (const float*)d_in[22];
    const float* Wr3  = (const float*)d_in[23];
    const float* br3  = (const float*)d_in[24];
    const float* w0   = (const float*)d_in[25];
    const float* w1   = (const float*)d_in[26];
    const float* w2   = (const float*)d_in[27];
    const float* w3   = (const float*)d_in[28];
    float* out = (float*)d_out;

    const int n = in_sizes[0] / 64;
    const int E = in_sizes[1] / 2;

    const int TB = 256;
    const int gE  = (E + TB - 1) / TB;
    const int gW2 = (2 * n * 32 + TB - 1) / TB;
    const int gW  = (n * 32 + TB - 1) / TB;
    const int gG  = (n + 127) / 128;
    const int nch = (n + 4095) / 4096;

    float* R0 = nullptr; __half* R0h = nullptr; __half* Yh = nullptr;
    __half* Rh = nullptr;
    float* R1 = nullptr; float* R2 = nullptr; float* R3 = nullptr;
    cudaGetSymbolAddress((void**)&R0,  g_R0);
    cudaGetSymbolAddress((void**)&R0h, g_R0h);
    cudaGetSymbolAddress((void**)&Yh,  g_yh);
    cudaGetSymbolAddress((void**)&Rh,  g_Rh);
    cudaGetSymbolAddress((void**)&R1,  g_R1);
    cudaGetSymbolAddress((void**)&R2,  g_R2);
    cudaGetSymbolAddress((void**)&R3,  g_R3);

    // dyn-smem sizes: (128*KP + KDIM*NP) * 2 bytes
    const int SM_R0   = (128 * 72  + 64  * 72 ) * 2;   // 27648
    const int SM_D64  = (128 * 72  + 64  * 136) * 2;   // 35840
    const int SM_D128 = (128 * 136 + 128 * 136) * 2;   // 69632 (>48KB -> opt in)
    cudaFuncSetAttribute(mma_gemm_kernel<128, true, true>,
                         cudaFuncAttributeMaxDynamicSharedMemorySize, SM_D128);

    // --- CSR build for both graphs ---
    zero_cnt_kernel<<<(2 * n + TB - 1) / TB, TB>>>(n);
    hist_kernel<<<gE, TB>>>(ei1, ei2, E);
    scan_partial<<<2 * nch, TB>>>(n, nch);
    scan_bsum<<<1, 64>>>(n, nch);
    scan_final<<<2 * nch, TB>>>(n, nch);
    scatter_kernel<<<gE, TB>>>(ei1, ei2, E);

    // --- R0 = relu(x @ W_in + b_in) : fp32 + fp16 copies ---
    mma_gemm_kernel<64, false, false><<<gG, TB, SM_R0>>>(
        x, W_in, nullptr, b_in, R0, R0h, n);

    // --- layer 1 ---
    mma_gemm_kernel<64, true, true><<<gG, TB, SM_D64>>>(
        R0h, W11, W12, nullptr, nullptr, Yh, n);
    agg2_kernel<<<gW2, TB>>>(Yh, b11, b12, R1, Rh, n);

    // --- layer 2 ---
    mma_gemm_kernel<128, true, true><<<gG, TB, SM_D128>>>(
        Rh, W21, W22, nullptr, nullptr, Yh, n);
    agg2_kernel<<<gW2, TB>>>(Yh, b21, b22, R2, Rh, n);

    // --- layer 3 ---
    mma_gemm_kernel<128, true, true><<<gG, TB, SM_D128>>>(
        Rh, W31, W32, nullptr, nullptr, Yh, n);
    agg2_kernel<<<gW2, TB>>>(Yh, b31, b32, R3, nullptr, n);

    // --- readout ---
    readout_kernel<<<gW, TB>>>(Wr0, br0, Wr1, br1, Wr2, br2, Wr3, br3,
                               w0, w1, w2, w3, out, n);
}

// round 10
// speedup vs baseline: 2.1560x; 1.0610x over previous
#include <cuda_runtime.h>
#include <cuda_fp16.h>
#include <cstdint>

#define NMAX 50000
#define EMAX 800000

// ---------------- scratch (device globals: no runtime allocation) -------------
__device__ int   g_cnt[2][NMAX];
__device__ int   g_offs[2][NMAX + 1];
__device__ int   g_cursor[2][NMAX];
__device__ int2  g_edge[2][EMAX];          // {row, __float_as_int(norm)} per CSR slot
__device__ float g_dinv[2][NMAX];
__device__ int   g_bsum[2][64];

__device__ __half g_R0h[NMAX * 64];        // fp16 R0 (GEMM input + readout)
__device__ __half g_yh[NMAX * 128];        // fp16 GEMM output consumed by aggregation
__device__ __half g_R1h[NMAX * 128];
__device__ __half g_R2h[NMAX * 128];
__device__ __half g_R3h[NMAX * 128];

// ---------------- CSR build ---------------------------------------------------
__global__ void zero_cnt_kernel(int n) {
    int i = blockIdx.x * blockDim.x + threadIdx.x;
    if (i < 2 * n) (&g_cnt[0][0])[i] = 0;
}

__global__ void hist_kernel(const int* __restrict__ ei1, const int* __restrict__ ei2, int E) {
    int e = blockIdx.x * blockDim.x + threadIdx.x;
    if (e < E) {
        atomicAdd(&g_cnt[0][ei1[E + e]], 1);
        atomicAdd(&g_cnt[1][ei2[E + e]], 1);
    }
}

// phase 1: per-chunk (4096-elem) sums. grid = 2*nch blocks of 256.
__global__ void scan_partial(int n, int nch) {
    int b = blockIdx.x;
    int g = b / nch, c = b % nch;
    const int* __restrict__ cnt = g_cnt[g];
    int i0 = c * 4096 + threadIdx.x * 16;
    int tot = 0;
    #pragma unroll
    for (int j = 0; j < 16; j++) {
        int i = i0 + j;
        if (i < n) tot += cnt[i];
    }
    #pragma unroll
    for (int o = 16; o; o >>= 1) tot += __shfl_xor_sync(0xffffffffu, tot, o);
    __shared__ int ws[8];
    if ((threadIdx.x & 31) == 0) ws[threadIdx.x >> 5] = tot;
    __syncthreads();
    if (threadIdx.x == 0) {
        int s = 0;
        #pragma unroll
        for (int k = 0; k < 8; k++) s += ws[k];
        g_bsum[g][c] = s;
    }
}

// phase 2 (fused): per-chunk rescan; chunk base computed inline from g_bsum.
__global__ void scan_final(int n, int nch) {
    int b = blockIdx.x;
    int g = b / nch, c = b % nch;
    const int* __restrict__ cnt = g_cnt[g];
    int* __restrict__ offs = g_offs[g];
    int* __restrict__ cur  = g_cursor[g];
    float* __restrict__ dinv = g_dinv[g];

    int base = 0;
    for (int k = 0; k < c; k++) base += g_bsum[g][k];   // <=13 iterations

    int i0 = c * 4096 + threadIdx.x * 16;
    int v[16];
    int tsum = 0;
    #pragma unroll
    for (int j = 0; j < 16; j++) {
        int i = i0 + j;
        v[j] = (i < n) ? cnt[i] : 0;
        tsum += v[j];
    }
    const int lane = threadIdx.x & 31;
    const int wid  = threadIdx.x >> 5;
    int s = tsum;
    #pragma unroll
    for (int o = 1; o < 32; o <<= 1) {
        int t = __shfl_up_sync(0xffffffffu, s, o);
        if (lane >= o) s += t;
    }
    __shared__ int ws[8];
    if (lane == 31) ws[wid] = s;
    __syncthreads();
    int woff = 0;
    if (wid > 0) {
        #pragma unroll
        for (int k = 0; k < 7; k++) if (k < wid) woff += ws[k];
    }
    int run = base + woff + (s - tsum);
    #pragma unroll
    for (int j = 0; j < 16; j++) {
        int i = i0 + j;
        if (i < n) {
            offs[i] = run;
            cur[i]  = run;
            dinv[i] = v[j] > 0 ? rsqrtf((float)v[j]) : 0.f;
        }
        run += v[j];
    }
    // last chunk, last thread holds the grand total
    if (c == nch - 1 && threadIdx.x == blockDim.x - 1) offs[n] = run;
}

__global__ void scatter_kernel(const int* __restrict__ ei1, const int* __restrict__ ei2, int E) {
    int e = blockIdx.x * blockDim.x + threadIdx.x;
    if (e < E) {
        int r = ei1[e], c = ei1[E + e];
        int p = atomicAdd(&g_cursor[0][c], 1);
        float nm = g_dinv[0][c] * g_dinv[0][r];
        g_edge[0][p] = make_int2(r, __float_as_int(nm));
        r = ei2[e]; c = ei2[E + e];
        p = atomicAdd(&g_cursor[1][c], 1);
        nm = g_dinv[1][c] * g_dinv[1][r];
        g_edge[1][p] = make_int2(r, __float_as_int(nm));
    }
}

// ---------------- tensor-core GEMM -------------------------------------------
__device__ __forceinline__ uint32_t smem_u32(const void* p) {
    uint32_t a;
    asm volatile("{ .reg .u64 t; cvta.to.shared.u64 t, %1; cvt.u32.u64 %0, t; }"
                 : "=r"(a) : "l"(p));
    return a;
}

__device__ __forceinline__ void mma16816(float* c, const uint32_t* a, const uint32_t* b) {
    asm volatile(
        "mma.sync.aligned.m16n8k16.row.col.f32.f16.f16.f32 "
        "{%0,%1,%2,%3},{%4,%5,%6,%7},{%8,%9},{%0,%1,%2,%3};"
        : "+f"(c[0]), "+f"(c[1]), "+f"(c[2]), "+f"(c[3])
        : "r"(a[0]), "r"(a[1]), "r"(a[2]), "r"(a[3]), "r"(b[0]), "r"(b[1]));
}

// C[M,NB] = X[M,KDIM] @ [Wa|Wb][KDIM,NB], fp16 in, fp32 accum, fp16 out.
// DUAL: NB=128 (Wa|Wb). !DUAL: NB=64, bias+relu. XHALF: X fp16 else fp32.
template<int KDIM, bool DUAL, bool XHALF>
__global__ __launch_bounds__(256) void mma_gemm_kernel(
    const void* __restrict__ Xv, const float* __restrict__ Wa,
    const float* __restrict__ Wb, const float* __restrict__ bias,
    __half* __restrict__ Yh, int M)
{
    constexpr int NB = DUAL ? 128 : 64;
    constexpr int KP = KDIM + 8;
    constexpr int NP = NB + 8;
    constexpr int NT = (NB / 2) / 8;
    constexpr int KT = KDIM / 16;

    extern __shared__ __align__(16) char dynsmem[];
    __half* Xs = (__half*)dynsmem;
    __half* Ws = Xs + 128 * KP;

    const int tid = threadIdx.x;
    const int row0 = blockIdx.x * 128;

    if (XHALF) {
        const __half* Xh = (const __half*)Xv;
        constexpr int XU = 128 * KDIM / 8;
        #pragma unroll
        for (int u = tid; u < XU; u += 256) {
            int r = u / (KDIM / 8), q = u % (KDIM / 8);
            uint4 v = make_uint4(0u, 0u, 0u, 0u);
            if (row0 + r < M)
                v = *(const uint4*)(Xh + (size_t)(row0 + r) * KDIM + q * 8);
            *(uint4*)&Xs[r * KP + q * 8] = v;
        }
    } else {
        const float* Xf = (const float*)Xv;
        constexpr int XU = 128 * KDIM / 4;
        #pragma unroll
        for (int u = tid; u < XU; u += 256) {
            int r = u / (KDIM / 4), q = u % (KDIM / 4);
            float4 v = make_float4(0.f, 0.f, 0.f, 0.f);
            if (row0 + r < M)
                v = *(const float4*)(Xf + (size_t)(row0 + r) * KDIM + q * 4);
            union { __half2 h[2]; uint2 u2; } t;
            t.h[0] = __floats2half2_rn(v.x, v.y);
            t.h[1] = __floats2half2_rn(v.z, v.w);
            *(uint2*)&Xs[r * KP + q * 4] = t.u2;
        }
    }
    {
        constexpr int WU = KDIM * 16 * (DUAL ? 2 : 1);
        #pragma unroll
        for (int u = tid; u < WU; u += 256) {
            int mat = DUAL ? (u >= KDIM * 16 ? 1 : 0) : 0;
            int v = u - mat * KDIM * 16;
            int k = v >> 4, q = v & 15;
            float4 w = *(const float4*)((mat ? Wb : Wa) + (size_t)k * 64 + q * 4);
            union { __half2 h[2]; uint2 u2; } t;
            t.h[0] = __floats2half2_rn(w.x, w.y);
            t.h[1] = __floats2half2_rn(w.z, w.w);
            *(uint2*)&Ws[k * NP + mat * 64 + q * 4] = t.u2;
        }
    }
    __syncthreads();

    const int wid = tid >> 5, lane = tid & 31;
    const int wm = (wid & 3) * 32;
    const int wn = (wid >> 2) * (NB / 2);
    const uint32_t xs0 = smem_u32(Xs);
    const uint32_t ws0 = smem_u32(Ws);

    float acc[2][NT][4];
    #pragma unroll
    for (int mt = 0; mt < 2; mt++)
        #pragma unroll
        for (int nt = 0; nt < NT; nt++)
            #pragma unroll
            for (int j = 0; j < 4; j++) acc[mt][nt][j] = 0.f;

    const int lr = lane & 15;
    const int lc = (lane >> 4) * 8;

    #pragma unroll
    for (int kk = 0; kk < KT; kk++) {
        uint32_t a[2][4];
        #pragma unroll
        for (int mt = 0; mt < 2; mt++) {
            uint32_t addr = xs0 + ((wm + mt * 16 + lr) * KP + kk * 16 + lc) * 2;
            asm volatile("ldmatrix.sync.aligned.m8n8.x4.shared.b16 {%0,%1,%2,%3},[%4];"
                         : "=r"(a[mt][0]), "=r"(a[mt][1]), "=r"(a[mt][2]), "=r"(a[mt][3])
                         : "r"(addr));
        }
        uint32_t b[NT][2];
        #pragma unroll
        for (int bt = 0; bt < NT / 2; bt++) {
            uint32_t addr = ws0 + ((kk * 16 + lr) * NP + wn + bt * 16 + lc) * 2;
            asm volatile("ldmatrix.sync.aligned.m8n8.x4.trans.shared.b16 {%0,%1,%2,%3},[%4];"
                         : "=r"(b[2 * bt][0]), "=r"(b[2 * bt][1]),
                           "=r"(b[2 * bt + 1][0]), "=r"(b[2 * bt + 1][1])
                         : "r"(addr));
        }
        #pragma unroll
        for (int mt = 0; mt < 2; mt++)
            #pragma unroll
            for (int nt = 0; nt < NT; nt++)
                mma16816(acc[mt][nt], a[mt], b[nt]);
    }

    const int gid = lane >> 2;
    const int t4  = (lane & 3) * 2;
    #pragma unroll
    for (int mt = 0; mt < 2; mt++) {
        #pragma unroll
        for (int nt = 0; nt < NT; nt++) {
            int col = wn + nt * 8 + t4;
            float o0 = acc[mt][nt][0], o1 = acc[mt][nt][1];
            float o2 = acc[mt][nt][2], o3 = acc[mt][nt][3];
            if (!DUAL) {
                float b0 = __ldg(bias + col), b1 = __ldg(bias + col + 1);
                o0 = fmaxf(o0 + b0, 0.f); o1 = fmaxf(o1 + b1, 0.f);
                o2 = fmaxf(o2 + b0, 0.f); o3 = fmaxf(o3 + b1, 0.f);
            }
            int r0 = row0 + wm + mt * 16 + gid;
            if (r0 < M)
                *(__half2*)&Yh[(size_t)r0 * NB + col] = __floats2half2_rn(o0, o1);
            int r1 = r0 + 8;
            if (r1 < M)
                *(__half2*)&Yh[(size_t)r1 * NB + col] = __floats2half2_rn(o2, o3);
        }
    }
}

// ---------------- fused dual-graph aggregation (fp16 gather, fp32 accum) ------
__global__ __launch_bounds__(256) void agg2_kernel(
    const __half* __restrict__ y,
    const float* __restrict__ biasA, const float* __restrict__ biasB,
    __half* __restrict__ Rh, int n)
{
    int w = (blockIdx.x * blockDim.x + threadIdx.x) >> 5;
    if (w >= 2 * n) return;
    const int g = (w >= n) ? 1 : 0;
    const int node = w - g * n;
    const int lane = threadIdx.x & 31;

    const int* __restrict__ offs = g_offs[g];
    const int2* __restrict__ ed = g_edge[g];
    const __half* __restrict__ ys = y + g * 64 + 2 * lane;

    int s = offs[node], e = offs[node + 1];
    float ax = 0.f, ay = 0.f;
    int i = s;
    for (; i + 4 <= e; i += 4) {
        int2 e0 = ed[i], e1 = ed[i + 1], e2 = ed[i + 2], e3 = ed[i + 3];
        float2 v0 = __half22float2(*(const __half2*)(ys + (size_t)e0.x * 128));
        float2 v1 = __half22float2(*(const __half2*)(ys + (size_t)e1.x * 128));
        float2 v2 = __half22float2(*(const __half2*)(ys + (size_t)e2.x * 128));
        float2 v3 = __half22float2(*(const __half2*)(ys + (size_t)e3.x * 128));
        float n0 = __int_as_float(e0.y), n1 = __int_as_float(e1.y);
        float n2 = __int_as_float(e2.y), n3 = __int_as_float(e3.y);
        ax += v0.x * n0 + v1.x * n1 + v2.x * n2 + v3.x * n3;
        ay += v0.y * n0 + v1.y * n1 + v2.y * n2 + v3.y * n3;
    }
    for (; i < e; i++) {
        int2 ee = ed[i];
        float2 v = __half22float2(*(const __half2*)(ys + (size_t)ee.x * 128));
        float nm = __int_as_float(ee.y);
        ax += v.x * nm;
        ay += v.y * nm;
    }
    const float* bp = g ? biasB : biasA;
    float2 b2 = *(const float2*)(bp + 2 * lane);
    *(__half2*)(Rh + (size_t)node * 128 + g * 64 + 2 * lane) =
        __floats2half2_rn(ax + b2.x, ay + b2.y);
}

// ---------------- readout (fp16 activations, fp32 weights/accum) ---------------
__global__ __launch_bounds__(256) void readout_kernel(
    const float* __restrict__ Wr0, const float* __restrict__ br0,
    const float* __restrict__ Wr1, const float* __restrict__ br1,
    const float* __restrict__ Wr2, const float* __restrict__ br2,
    const float* __restrict__ Wr3, const float* __restrict__ br3,
    const float* __restrict__ w0, const float* __restrict__ w1,
    const float* __restrict__ w2, const float* __restrict__ w3,
    float* __restrict__ out, int n)
{
    int node = (blockIdx.x * blockDim.x + threadIdx.x) >> 5;
    if (node >= n) return;
    const int lane = threadIdx.x & 31;
    float W0 = w0[0], W1 = w1[0], W2 = w2[0], W3 = w3[0];
    float p = 0.f;
    {
        float2 r = __half22float2(*(const __half2*)(g_R0h + (size_t)node * 64 + 2 * lane));
        float2 w = *(const float2*)(Wr0 + 2 * lane);
        p += W0 * (r.x * w.x + r.y * w.y);
    }
    {
        uint2 u = *(const uint2*)(g_R1h + (size_t)node * 128 + 4 * lane);
        float2 ra = __half22float2(*(__half2*)&u.x);
        float2 rb = __half22float2(*(__half2*)&u.y);
        float4 w = *(const float4*)(Wr1 + 4 * lane);
        p += W1 * (ra.x * w.x + ra.y * w.y + rb.x * w.z + rb.y * w.w);
    }
    {
        uint2 u = *(const uint2*)(g_R2h + (size_t)node * 128 + 4 * lane);
        float2 ra = __half22float2(*(__half2*)&u.x);
        float2 rb = __half22float2(*(__half2*)&u.y);
        float4 w = *(const float4*)(Wr2 + 4 * lane);
        p += W2 * (ra.x * w.x + ra.y * w.y + rb.x * w.z + rb.y * w.w);
    }
    {
        uint2 u = *(const uint2*)(g_R3h + (size_t)node * 128 + 4 * lane);
        float2 ra = __half22float2(*(__half2*)&u.x);
        float2 rb = __half22float2(*(__half2*)&u.y);
        float4 w = *(const float4*)(Wr3 + 4 * lane);
        p += W3 * (ra.x * w.x + ra.y * w.y + rb.x * w.z + rb.y * w.w);
    }
    #pragma unroll
    for (int o = 16; o; o >>= 1) p += __shfl_xor_sync(0xffffffffu, p, o);
    if (lane == 0)
        out[node] = p + W0 * br0[0] + W1 * br1[0] + W2 * br2[0] + W3 * br3[0];
}

// ---------------- launch ------------------------------------------------------
extern "C" void kernel_launch(void* const* d_in, const int* in_sizes, int n_in,
                              void* d_out, int out_size)
{
    const float* x    = (const float*)d_in[0];
    const int*   ei1  = (const int*)d_in[1];
    const int*   ei2  = (const int*)d_in[2];
    const float* W_in = (const float*)d_in[3];
    const float* b_in = (const float*)d_in[4];
    const float* W11  = (const float*)d_in[5];
    const float* b11  = (const float*)d_in[6];
    const float* W12  = (const float*)d_in[7];
    const float* b12  = (const float*)d_in[8];
    const float* W21  = (const float*)d_in[9];
    const float* b21  = (const float*)d_in[10];
    const float* W22  = (const float*)d_in[11];
    const float* b22  = (const float*)d_in[12];
    const float* W31  = (const float*)d_in[13];
    const float* b31  = (const float*)d_in[14];
    const float* W32  = (const float*)d_in[15];
    const float* b32  = (const float*)d_in[16];
    const float* Wr0  = (const float*)d_in[17];
    const float* br0  = (const float*)d_in[18];
    const float* Wr1  = (const float*)d_in[19];
    const float* br1  = (const float*)d_in[20];
    const float* Wr2  = (const float*)d_in[21];
    const float* br2  = (const float*)d_in[22];
    const float* Wr3  = (const float*)d_in[23];
    const float* br3  = (const float*)d_in[24];
    const float* w0   = (const float*)d_in[25];
    const float* w1   = (const float*)d_in[26];
    const float* w2   = (const float*)d_in[27];
    const float* w3   = (const float*)d_in[28];
    float* out = (float*)d_out;

    const int n = in_sizes[0] / 64;
    const int E = in_sizes[1] / 2;

    const int TB = 256;
    const int gE  = (E + TB - 1) / TB;
    const int gW2 = (2 * n * 32 + TB - 1) / TB;
    const int gW  = (n * 32 + TB - 1) / TB;
    const int gG  = (n + 127) / 128;
    const int nch = (n + 4095) / 4096;

    __half* R0h = nullptr; __half* Yh = nullptr;
    __half* R1h = nullptr; __half* R2h = nullptr; __half* R3h = nullptr;
    cudaGetSymbolAddress((void**)&R0h, g_R0h);
    cudaGetSymbolAddress((void**)&Yh,  g_yh);
    cudaGetSymbolAddress((void**)&R1h, g_R1h);
    cudaGetSymbolAddress((void**)&R2h, g_R2h);
    cudaGetSymbolAddress((void**)&R3h, g_R3h);

    const int SM_R0   = (128 * 72  + 64  * 72 ) * 2;
    const int SM_D64  = (128 * 72  + 64  * 136) * 2;
    const int SM_D128 = (128 * 136 + 128 * 136) * 2;   // 69632 (>48KB -> opt in)
    cudaFuncSetAttribute(mma_gemm_kernel<128, true, true>,
                         cudaFuncAttributeMaxDynamicSharedMemorySize, SM_D128);

    // --- CSR build for both graphs ---
    zero_cnt_kernel<<<(2 * n + TB - 1) / TB, TB>>>(n);
    hist_kernel<<<gE, TB>>>(ei1, ei2, E);
    scan_partial<<<2 * nch, TB>>>(n, nch);
    scan_final<<<2 * nch, TB>>>(n, nch);
    scatter_kernel<<<gE, TB>>>(ei1, ei2, E);

    // --- R0 = relu(x @ W_in + b_in), fp16 ---
    mma_gemm_kernel<64, false, false><<<gG, TB, SM_R0>>>(
        x, W_in, nullptr, b_in, R0h, n);

    // --- layer 1 ---
    mma_gemm_kernel<64, true, true><<<gG, TB, SM_D64>>>(
        R0h, W11, W12, nullptr, Yh, n);
    agg2_kernel<<<gW2, TB>>>(Yh, b11, b12, R1h, n);

    // --- layer 2 ---
    mma_gemm_kernel<128, true, true><<<gG, TB, SM_D128>>>(
        R1h, W21, W22, nullptr, Yh, n);
    agg2_kernel<<<gW2, TB>>>(Yh, b21, b22, R2h, n);

    // --- layer 3 ---
    mma_gemm_kernel<128, true, true><<<gG, TB, SM_D128>>>(
        R2h, W31, W32, nullptr, Yh, n);
    agg2_kernel<<<gW2, TB>>>(Yh, b31, b32, R3h, n);

    // --- readout ---
    readout_kernel<<<gW, TB>>>(Wr0, br0, Wr1, br1, Wr2, br2, Wr3, br3,
                               w0, w1, w2, w3, out, n);
}

// round 11
// speedup vs baseline: 2.2539x; 1.0454x over previous
#include <cuda_runtime.h>
#include <cuda_fp16.h>
#include <cstdint>

#define NMAX 50000
#define EMAX 800000

// ---------------- scratch (device globals: no runtime allocation) -------------
__device__ int   g_cnt[2][NMAX];
__device__ int   g_offs[2][NMAX + 1];
__device__ int   g_cursor[2][NMAX];
__device__ int2  g_edge[2][EMAX];          // {row, __float_as_int(norm)} per CSR slot
__device__ float g_dinv[2][NMAX];
__device__ int   g_bsum[2][64];

__device__ __half g_R0h[NMAX * 64];        // fp16 R0 (readout input)
__device__ __half g_yh[NMAX * 128];        // fp16 GEMM output consumed by aggregation
__device__ __half g_R1h[NMAX * 128];
__device__ __half g_R2h[NMAX * 128];
__device__ __half g_R3h[NMAX * 128];

#define SCAN_CHUNK 1024

// ---------------- CSR build ---------------------------------------------------
__global__ void zero_cnt_kernel(int n) {
    int i = blockIdx.x * blockDim.x + threadIdx.x;
    if (i < 2 * n) (&g_cnt[0][0])[i] = 0;
}

__global__ void hist_kernel(const int* __restrict__ ei1, const int* __restrict__ ei2, int E) {
    int e = blockIdx.x * blockDim.x + threadIdx.x;
    if (e < E) {
        atomicAdd(&g_cnt[0][ei1[E + e]], 1);
        atomicAdd(&g_cnt[1][ei2[E + e]], 1);
    }
}

// phase 1: per-chunk (1024-elem) sums. grid = 2*nch blocks of 256.
__global__ void scan_partial(int n, int nch) {
    int b = blockIdx.x;
    int g = b / nch, c = b % nch;
    const int* __restrict__ cnt = g_cnt[g];
    int i0 = c * SCAN_CHUNK + threadIdx.x * 4;
    int tot = 0;
    #pragma unroll
    for (int j = 0; j < 4; j++) {
        int i = i0 + j;
        if (i < n) tot += cnt[i];
    }
    #pragma unroll
    for (int o = 16; o; o >>= 1) tot += __shfl_xor_sync(0xffffffffu, tot, o);
    __shared__ int ws[8];
    if ((threadIdx.x & 31) == 0) ws[threadIdx.x >> 5] = tot;
    __syncthreads();
    if (threadIdx.x == 0) {
        int s = 0;
        #pragma unroll
        for (int k = 0; k < 8; k++) s += ws[k];
        g_bsum[g][c] = s;
    }
}

// phase 2: per-chunk rescan; chunk base computed inline from g_bsum.
__global__ void scan_final(int n, int nch) {
    int b = blockIdx.x;
    int g = b / nch, c = b % nch;
    const int* __restrict__ cnt = g_cnt[g];
    int* __restrict__ offs = g_offs[g];
    int* __restrict__ cur  = g_cursor[g];
    float* __restrict__ dinv = g_dinv[g];

    int base = 0;
    for (int k = 0; k < c; k++) base += g_bsum[g][k];   // <= nch-1 iters (L1-hot)

    int i0 = c * SCAN_CHUNK + threadIdx.x * 4;
    int v[4];
    int tsum = 0;
    #pragma unroll
    for (int j = 0; j < 4; j++) {
        int i = i0 + j;
        v[j] = (i < n) ? cnt[i] : 0;
        tsum += v[j];
    }
    const int lane = threadIdx.x & 31;
    const int wid  = threadIdx.x >> 5;
    int s = tsum;
    #pragma unroll
    for (int o = 1; o < 32; o <<= 1) {
        int t = __shfl_up_sync(0xffffffffu, s, o);
        if (lane >= o) s += t;
    }
    __shared__ int ws[8];
    if (lane == 31) ws[wid] = s;
    __syncthreads();
    int woff = 0;
    if (wid > 0) {
        #pragma unroll
        for (int k = 0; k < 7; k++) if (k < wid) woff += ws[k];
    }
    int run = base + woff + (s - tsum);
    #pragma unroll
    for (int j = 0; j < 4; j++) {
        int i = i0 + j;
        if (i < n) {
            offs[i] = run;
            cur[i]  = run;
            dinv[i] = v[j] > 0 ? rsqrtf((float)v[j]) : 0.f;
        }
        run += v[j];
    }
    if (c == nch - 1 && threadIdx.x == blockDim.x - 1) offs[n] = run;
}

__global__ void scatter_kernel(const int* __restrict__ ei1, const int* __restrict__ ei2, int E) {
    int e = blockIdx.x * blockDim.x + threadIdx.x;
    if (e < E) {
        int r = ei1[e], c = ei1[E + e];
        int p = atomicAdd(&g_cursor[0][c], 1);
        float nm = g_dinv[0][c] * g_dinv[0][r];
        g_edge[0][p] = make_int2(r, __float_as_int(nm));
        r = ei2[e]; c = ei2[E + e];
        p = atomicAdd(&g_cursor[1][c], 1);
        nm = g_dinv[1][c] * g_dinv[1][r];
        g_edge[1][p] = make_int2(r, __float_as_int(nm));
    }
}

// ---------------- tensor-core GEMM helpers -------------------------------------
__device__ __forceinline__ uint32_t smem_u32(const void* p) {
    uint32_t a;
    asm volatile("{ .reg .u64 t; cvta.to.shared.u64 t, %1; cvt.u32.u64 %0, t; }"
                 : "=r"(a) : "l"(p));
    return a;
}

__device__ __forceinline__ void mma16816(float* c, const uint32_t* a, const uint32_t* b) {
    asm volatile(
        "mma.sync.aligned.m16n8k16.row.col.f32.f16.f16.f32 "
        "{%0,%1,%2,%3},{%4,%5,%6,%7},{%8,%9},{%0,%1,%2,%3};"
        : "+f"(c[0]), "+f"(c[1]), "+f"(c[2]), "+f"(c[3])
        : "r"(a[0]), "r"(a[1]), "r"(a[2]), "r"(a[3]), "r"(b[0]), "r"(b[1]));
}

// load W[KDIM x 64] fp32 -> fp16 smem with stride NP, col offset co
template<int KDIM, int NP>
__device__ __forceinline__ void load_w_tile(const float* __restrict__ W,
                                            __half* Ws, int co, int tid) {
    constexpr int WU = KDIM * 16;
    #pragma unroll
    for (int u = tid; u < WU; u += 256) {
        int k = u >> 4, q = u & 15;
        float4 w = *(const float4*)(W + (size_t)k * 64 + q * 4);
        union { __half2 h[2]; uint2 u2; } t;
        t.h[0] = __floats2half2_rn(w.x, w.y);
        t.h[1] = __floats2half2_rn(w.z, w.w);
        *(uint2*)&Ws[k * NP + co + q * 4] = t.u2;
    }
}

// one GEMM mainloop: acc[2][NT][4] += A(128xKDIM, stride KP) * B(KDIMxNB, stride NP)
template<int KDIM, int KP, int NB, int NP, int NT>
__device__ __forceinline__ void mma_mainloop(
    float acc[2][NT][4], uint32_t xs0, uint32_t ws0, int wm, int wn, int lane)
{
    const int lr = lane & 15;
    const int lc = (lane >> 4) * 8;
    #pragma unroll
    for (int kk = 0; kk < KDIM / 16; kk++) {
        uint32_t a[2][4];
        #pragma unroll
        for (int mt = 0; mt < 2; mt++) {
            uint32_t addr = xs0 + ((wm + mt * 16 + lr) * KP + kk * 16 + lc) * 2;
            asm volatile("ldmatrix.sync.aligned.m8n8.x4.shared.b16 {%0,%1,%2,%3},[%4];"
                         : "=r"(a[mt][0]), "=r"(a[mt][1]), "=r"(a[mt][2]), "=r"(a[mt][3])
                         : "r"(addr));
        }
        uint32_t b[NT][2];
        #pragma unroll
        for (int bt = 0; bt < NT / 2; bt++) {
            uint32_t addr = ws0 + ((kk * 16 + lr) * NP + wn + bt * 16 + lc) * 2;
            asm volatile("ldmatrix.sync.aligned.m8n8.x4.trans.shared.b16 {%0,%1,%2,%3},[%4];"
                         : "=r"(b[2 * bt][0]), "=r"(b[2 * bt][1]),
                           "=r"(b[2 * bt + 1][0]), "=r"(b[2 * bt + 1][1])
                         : "r"(addr));
        }
        #pragma unroll
        for (int mt = 0; mt < 2; mt++)
            #pragma unroll
            for (int nt = 0; nt < NT; nt++)
                mma16816(acc[mt][nt], a[mt], b[nt]);
    }
}

// ---------------- fused R0 + layer-1 dual GEMM ---------------------------------
// phase 1: R0 = relu(x[128,64] @ W_in + b_in)  -> smem + global R0h
// phase 2: Yh[128,128] = R0 @ [W11|W12]
__global__ __launch_bounds__(256) void fused_in_l1_kernel(
    const float* __restrict__ X, const float* __restrict__ W_in,
    const float* __restrict__ b_in, const float* __restrict__ W11,
    const float* __restrict__ W12, __half* __restrict__ R0h,
    __half* __restrict__ Yh, int M)
{
    constexpr int KP = 72;      // x / R0 tile stride
    constexpr int NPA = 72;     // W_in stride
    constexpr int NPB = 136;    // [W11|W12] stride
    extern __shared__ __align__(16) char dynsmem[];
    __half* Xs  = (__half*)dynsmem;            // 128*72
    __half* Wi  = Xs + 128 * KP;               // 64*72
    __half* R0s = Wi + 64 * NPA;               // 128*72
    __half* W1s = R0s + 128 * KP;              // 64*136

    const int tid = threadIdx.x;
    const int row0 = blockIdx.x * 128;

    // load x tile fp32->fp16
    {
        constexpr int XU = 128 * 64 / 4;
        #pragma unroll
        for (int u = tid; u < XU; u += 256) {
            int r = u >> 4, q = (u & 15) * 4;
            float4 v = make_float4(0.f, 0.f, 0.f, 0.f);
            if (row0 + r < M)
                v = *(const float4*)(X + (size_t)(row0 + r) * 64 + q);
            union { __half2 h[2]; uint2 u2; } t;
            t.h[0] = __floats2half2_rn(v.x, v.y);
            t.h[1] = __floats2half2_rn(v.z, v.w);
            *(uint2*)&Xs[r * KP + q] = t.u2;
        }
    }
    load_w_tile<64, NPA>(W_in, Wi, 0, tid);
    load_w_tile<64, NPB>(W11, W1s, 0, tid);
    load_w_tile<64, NPB>(W12, W1s, 64, tid);
    __syncthreads();

    const int wid = tid >> 5, lane = tid & 31;
    const int wm = (wid & 3) * 32;
    const int gid = lane >> 2;
    const int t4  = (lane & 3) * 2;

    // ---- phase 1: NB=64, NT=4, wn = (wid>>2)*32 ----
    {
        const int wn = (wid >> 2) * 32;
        float acc[2][4][4];
        #pragma unroll
        for (int mt = 0; mt < 2; mt++)
            #pragma unroll
            for (int nt = 0; nt < 4; nt++)
                #pragma unroll
                for (int j = 0; j < 4; j++) acc[mt][nt][j] = 0.f;
        mma_mainloop<64, KP, 64, NPA, 4>(acc, smem_u32(Xs), smem_u32(Wi), wm, wn, lane);

        #pragma unroll
        for (int mt = 0; mt < 2; mt++) {
            #pragma unroll
            for (int nt = 0; nt < 4; nt++) {
                int col = wn + nt * 8 + t4;
                float b0 = __ldg(b_in + col), b1 = __ldg(b_in + col + 1);
                float o0 = fmaxf(acc[mt][nt][0] + b0, 0.f);
                float o1 = fmaxf(acc[mt][nt][1] + b1, 0.f);
                float o2 = fmaxf(acc[mt][nt][2] + b0, 0.f);
                float o3 = fmaxf(acc[mt][nt][3] + b1, 0.f);
                int lr0 = wm + mt * 16 + gid;
                __half2 h01 = __floats2half2_rn(o0, o1);
                __half2 h23 = __floats2half2_rn(o2, o3);
                *(__half2*)&R0s[lr0 * KP + col] = h01;
                *(__half2*)&R0s[(lr0 + 8) * KP + col] = h23;
                int g0 = row0 + lr0;
                if (g0 < M) *(__half2*)&R0h[(size_t)g0 * 64 + col] = h01;
                if (g0 + 8 < M) *(__half2*)&R0h[(size_t)(g0 + 8) * 64 + col] = h23;
            }
        }
    }
    __syncthreads();

    // ---- phase 2: NB=128, NT=8, wn = (wid>>2)*64 ----
    {
        const int wn = (wid >> 2) * 64;
        float acc[2][8][4];
        #pragma unroll
        for (int mt = 0; mt < 2; mt++)
            #pragma unroll
            for (int nt = 0; nt < 8; nt++)
                #pragma unroll
                for (int j = 0; j < 4; j++) acc[mt][nt][j] = 0.f;
        mma_mainloop<64, KP, 128, NPB, 8>(acc, smem_u32(R0s), smem_u32(W1s), wm, wn, lane);

        #pragma unroll
        for (int mt = 0; mt < 2; mt++) {
            #pragma unroll
            for (int nt = 0; nt < 8; nt++) {
                int col = wn + nt * 8 + t4;
                int r0 = row0 + wm + mt * 16 + gid;
                if (r0 < M)
                    *(__half2*)&Yh[(size_t)r0 * 128 + col] =
                        __floats2half2_rn(acc[mt][nt][0], acc[mt][nt][1]);
                if (r0 + 8 < M)
                    *(__half2*)&Yh[(size_t)(r0 + 8) * 128 + col] =
                        __floats2half2_rn(acc[mt][nt][2], acc[mt][nt][3]);
            }
        }
    }
}

// ---------------- dual GEMM (layers 2,3): X fp16 [M,128] -> Yh [M,128] ---------
__global__ __launch_bounds__(256) void mma_gemm128_kernel(
    const __half* __restrict__ Xh, const float* __restrict__ Wa,
    const float* __restrict__ Wb, __half* __restrict__ Yh, int M)
{
    constexpr int KP = 136, NP = 136;
    extern __shared__ __align__(16) char dynsmem[];
    __half* Xs = (__half*)dynsmem;         // 128*136
    __half* Ws = Xs + 128 * KP;            // 128*136

    const int tid = threadIdx.x;
    const int row0 = blockIdx.x * 128;

    {
        constexpr int XU = 128 * 128 / 8;
        #pragma unroll
        for (int u = tid; u < XU; u += 256) {
            int r = u >> 4, q = (u & 15) * 8;
            uint4 v = make_uint4(0u, 0u, 0u, 0u);
            if (row0 + r < M)
                v = *(const uint4*)(Xh + (size_t)(row0 + r) * 128 + q);
            *(uint4*)&Xs[r * KP + q] = v;
        }
    }
    load_w_tile<128, NP>(Wa, Ws, 0, tid);
    load_w_tile<128, NP>(Wb, Ws, 64, tid);
    __syncthreads();

    const int wid = tid >> 5, lane = tid & 31;
    const int wm = (wid & 3) * 32;
    const int wn = (wid >> 2) * 64;

    float acc[2][8][4];
    #pragma unroll
    for (int mt = 0; mt < 2; mt++)
        #pragma unroll
        for (int nt = 0; nt < 8; nt++)
            #pragma unroll
            for (int j = 0; j < 4; j++) acc[mt][nt][j] = 0.f;
    mma_mainloop<128, KP, 128, NP, 8>(acc, smem_u32(Xs), smem_u32(Ws), wm, wn, lane);

    const int gid = lane >> 2;
    const int t4  = (lane & 3) * 2;
    #pragma unroll
    for (int mt = 0; mt < 2; mt++) {
        #pragma unroll
        for (int nt = 0; nt < 8; nt++) {
            int col = wn + nt * 8 + t4;
            int r0 = row0 + wm + mt * 16 + gid;
            if (r0 < M)
                *(__half2*)&Yh[(size_t)r0 * 128 + col] =
                    __floats2half2_rn(acc[mt][nt][0], acc[mt][nt][1]);
            if (r0 + 8 < M)
                *(__half2*)&Yh[(size_t)(r0 + 8) * 128 + col] =
                    __floats2half2_rn(acc[mt][nt][2], acc[mt][nt][3]);
        }
    }
}

// ---------------- fused dual-graph aggregation (fp16 gather, fp32 accum) ------
__global__ __launch_bounds__(256) void agg2_kernel(
    const __half* __restrict__ y,
    const float* __restrict__ biasA, const float* __restrict__ biasB,
    __half* __restrict__ Rh, int n)
{
    int w = (blockIdx.x * blockDim.x + threadIdx.x) >> 5;
    if (w >= 2 * n) return;
    const int g = (w >= n) ? 1 : 0;
    const int node = w - g * n;
    const int lane = threadIdx.x & 31;

    const int* __restrict__ offs = g_offs[g];
    const int2* __restrict__ ed = g_edge[g];
    const __half* __restrict__ ys = y + g * 64 + 2 * lane;

    int s = offs[node], e = offs[node + 1];
    float ax = 0.f, ay = 0.f;
    int i = s;

    if (i + 4 <= e) {
        // software pipeline: prefetch next batch of edge records
        int2 p0 = ed[i], p1 = ed[i + 1], p2 = ed[i + 2], p3 = ed[i + 3];
        for (; i + 8 <= e; i += 4) {
            int2 q0 = ed[i + 4], q1 = ed[i + 5], q2 = ed[i + 6], q3 = ed[i + 7];
            float2 v0 = __half22float2(*(const __half2*)(ys + (size_t)p0.x * 128));
            float2 v1 = __half22float2(*(const __half2*)(ys + (size_t)p1.x * 128));
            float2 v2 = __half22float2(*(const __half2*)(ys + (size_t)p2.x * 128));
            float2 v3 = __half22float2(*(const __half2*)(ys + (size_t)p3.x * 128));
            ax += v0.x * __int_as_float(p0.y) + v1.x * __int_as_float(p1.y)
                + v2.x * __int_as_float(p2.y) + v3.x * __int_as_float(p3.y);
            ay += v0.y * __int_as_float(p0.y) + v1.y * __int_as_float(p1.y)
                + v2.y * __int_as_float(p2.y) + v3.y * __int_as_float(p3.y);
            p0 = q0; p1 = q1; p2 = q2; p3 = q3;
        }
        // drain the prefetched batch
        float2 v0 = __half22float2(*(const __half2*)(ys + (size_t)p0.x * 128));
        float2 v1 = __half22float2(*(const __half2*)(ys + (size_t)p1.x * 128));
        float2 v2 = __half22float2(*(const __half2*)(ys + (size_t)p2.x * 128));
        float2 v3 = __half22float2(*(const __half2*)(ys + (size_t)p3.x * 128));
        ax += v0.x * __int_as_float(p0.y) + v1.x * __int_as_float(p1.y)
            + v2.x * __int_as_float(p2.y) + v3.x * __int_as_float(p3.y);
        ay += v0.y * __int_as_float(p0.y) + v1.y * __int_as_float(p1.y)
            + v2.y * __int_as_float(p2.y) + v3.y * __int_as_float(p3.y);
        i += 4;
    }
    for (; i < e; i++) {
        int2 ee = ed[i];
        float2 v = __half22float2(*(const __half2*)(ys + (size_t)ee.x * 128));
        float nm = __int_as_float(ee.y);
        ax += v.x * nm;
        ay += v.y * nm;
    }
    const float* bp = g ? biasB : biasA;
    float2 b2 = *(const float2*)(bp + 2 * lane);
    *(__half2*)(Rh + (size_t)node * 128 + g * 64 + 2 * lane) =
        __floats2half2_rn(ax + b2.x, ay + b2.y);
}

// ---------------- readout (fp16 activations, fp32 weights/accum) ---------------
__global__ __launch_bounds__(256) void readout_kernel(
    const float* __restrict__ Wr0, const float* __restrict__ br0,
    const float* __restrict__ Wr1, const float* __restrict__ br1,
    const float* __restrict__ Wr2, const float* __restrict__ br2,
    const float* __restrict__ Wr3, const float* __restrict__ br3,
    const float* __restrict__ w0, const float* __restrict__ w1,
    const float* __restrict__ w2, const float* __restrict__ w3,
    float* __restrict__ out, int n)
{
    int node = (blockIdx.x * blockDim.x + threadIdx.x) >> 5;
    if (node >= n) return;
    const int lane = threadIdx.x & 31;
    float W0 = w0[0], W1 = w1[0], W2 = w2[0], W3 = w3[0];
    float p = 0.f;
    {
        float2 r = __half22float2(*(const __half2*)(g_R0h + (size_t)node * 64 + 2 * lane));
        float2 w = *(const float2*)(Wr0 + 2 * lane);
        p += W0 * (r.x * w.x + r.y * w.y);
    }
    {
        uint2 u = *(const uint2*)(g_R1h + (size_t)node * 128 + 4 * lane);
        float2 ra = __half22float2(*(__half2*)&u.x);
        float2 rb = __half22float2(*(__half2*)&u.y);
        float4 w = *(const float4*)(Wr1 + 4 * lane);
        p += W1 * (ra.x * w.x + ra.y * w.y + rb.x * w.z + rb.y * w.w);
    }
    {
        uint2 u = *(const uint2*)(g_R2h + (size_t)node * 128 + 4 * lane);
        float2 ra = __half22float2(*(__half2*)&u.x);
        float2 rb = __half22float2(*(__half2*)&u.y);
        float4 w = *(const float4*)(Wr2 + 4 * lane);
        p += W2 * (ra.x * w.x + ra.y * w.y + rb.x * w.z + rb.y * w.w);
    }
    {
        uint2 u = *(const uint2*)(g_R3h + (size_t)node * 128 + 4 * lane);
        float2 ra = __half22float2(*(__half2*)&u.x);
        float2 rb = __half22float2(*(__half2*)&u.y);
        float4 w = *(const float4*)(Wr3 + 4 * lane);
        p += W3 * (ra.x * w.x + ra.y * w.y + rb.x * w.z + rb.y * w.w);
    }
    #pragma unroll
    for (int o = 16; o; o >>= 1) p += __shfl_xor_sync(0xffffffffu, p, o);
    if (lane == 0)
        out[node] = p + W0 * br0[0] + W1 * br1[0] + W2 * br2[0] + W3 * br3[0];
}

// ---------------- launch ------------------------------------------------------
extern "C" void kernel_launch(void* const* d_in, const int* in_sizes, int n_in,
                              void* d_out, int out_size)
{
    const float* x    = (const float*)d_in[0];
    const int*   ei1  = (const int*)d_in[1];
    const int*   ei2  = (const int*)d_in[2];
    const float* W_in = (const float*)d_in[3];
    const float* b_in = (const float*)d_in[4];
    const float* W11  = (const float*)d_in[5];
    const float* b11  = (const float*)d_in[6];
    const float* W12  = (const float*)d_in[7];
    const float* b12  = (const float*)d_in[8];
    const float* W21  = (const float*)d_in[9];
    const float* b21  = (const float*)d_in[10];
    const float* W22  = (const float*)d_in[11];
    const float* b22  = (const float*)d_in[12];
    const float* W31  = (const float*)d_in[13];
    const float* b31  = (const float*)d_in[14];
    const float* W32  = (const float*)d_in[15];
    const float* b32  = (const float*)d_in[16];
    const float* Wr0  = (const float*)d_in[17];
    const float* br0  = (const float*)d_in[18];
    const float* Wr1  = (const float*)d_in[19];
    const float* br1  = (const float*)d_in[20];
    const float* Wr2  = (const float*)d_in[21];
    const float* br2  = (const float*)d_in[22];
    const float* Wr3  = (const float*)d_in[23];
    const float* br3  = (const float*)d_in[24];
    const float* w0   = (const float*)d_in[25];
    const float* w1   = (const float*)d_in[26];
    const float* w2   = (const float*)d_in[27];
    const float* w3   = (const float*)d_in[28];
    float* out = (float*)d_out;

    const int n = in_sizes[0] / 64;
    const int E = in_sizes[1] / 2;

    const int TB = 256;
    const int gE  = (E + TB - 1) / TB;
    const int gW2 = (2 * n * 32 + TB - 1) / TB;
    const int gW  = (n * 32 + TB - 1) / TB;
    const int gG  = (n + 127) / 128;
    const int nch = (n + SCAN_CHUNK - 1) / SCAN_CHUNK;

    __half* R0h = nullptr; __half* Yh = nullptr;
    __half* R1h = nullptr; __half* R2h = nullptr; __half* R3h = nullptr;
    cudaGetSymbolAddress((void**)&R0h, g_R0h);
    cudaGetSymbolAddress((void**)&Yh,  g_yh);
    cudaGetSymbolAddress((void**)&R1h, g_R1h);
    cudaGetSymbolAddress((void**)&R2h, g_R2h);
    cudaGetSymbolAddress((void**)&R3h, g_R3h);

    // smem: fused = (128*72 + 64*72 + 128*72 + 64*136)*2 = 63488 bytes
    //       gemm128 = (128*136 + 128*136)*2 = 69632 bytes
    const int SM_FUSED = (128 * 72 + 64 * 72 + 128 * 72 + 64 * 136) * 2;
    const int SM_D128  = (128 * 136 + 128 * 136) * 2;
    cudaFuncSetAttribute(fused_in_l1_kernel,
                         cudaFuncAttributeMaxDynamicSharedMemorySize, SM_FUSED);
    cudaFuncSetAttribute(mma_gemm128_kernel,
                         cudaFuncAttributeMaxDynamicSharedMemorySize, SM_D128);

    // --- CSR build for both graphs ---
    zero_cnt_kernel<<<(2 * n + TB - 1) / TB, TB>>>(n);
    hist_kernel<<<gE, TB>>>(ei1, ei2, E);
    scan_partial<<<2 * nch, TB>>>(n, nch);
    scan_final<<<2 * nch, TB>>>(n, nch);
    scatter_kernel<<<gE, TB>>>(ei1, ei2, E);

    // --- fused R0 + layer-1 dual GEMM ---
    fused_in_l1_kernel<<<gG, TB, SM_FUSED>>>(x, W_in, b_in, W11, W12, R0h, Yh, n);
    agg2_kernel<<<gW2, TB>>>(Yh, b11, b12, R1h, n);

    // --- layer 2 ---
    mma_gemm128_kernel<<<gG, TB, SM_D128>>>(R1h, W21, W22, Yh, n);
    agg2_kernel<<<gW2, TB>>>(Yh, b21, b22, R2h, n);

    // --- layer 3 ---
    mma_gemm128_kernel<<<gG, TB, SM_D128>>>(R2h, W31, W32, Yh, n);
    agg2_kernel<<<gW2, TB>>>(Yh, b31, b32, R3h, n);

    // --- readout ---
    readout_kernel<<<gW, TB>>>(Wr0, br0, Wr1, br1, Wr2, br2, Wr3, br3,
                               w0, w1, w2, w3, out, n);
}